// round 2
// baseline (speedup 1.0000x reference)
#include <cuda_runtime.h>
#include <cuda_bf16.h>
#include <math.h>

#define N_NODES 100000
#define N_EDGES 1000000

// ---------------- scratch (static device globals; no allocation) ----------------
__device__ int   g_count[N_NODES];
__device__ int   g_off[N_NODES + 1];
__device__ int   g_cur[N_NODES];
__device__ int   g_src_sorted[N_EDGES];
__device__ float g_inv_deg[N_NODES];
__device__ float g_agg[(size_t)N_NODES * 128];
__device__ float g_h1 [(size_t)N_NODES * 128];
__device__ float g_h2 [(size_t)N_NODES * 128];
__device__ float g_t  [(size_t)N_NODES * 80];
__device__ float g_wcat[128 * 80];

// ---------------- CSR construction ----------------
__global__ void zero_counts_kernel() {
    int i = blockIdx.x * blockDim.x + threadIdx.x;
    if (i < N_NODES) g_count[i] = 0;
}

__global__ void hist_kernel(const int* __restrict__ dst) {
    int e = blockIdx.x * blockDim.x + threadIdx.x;
    if (e < N_EDGES) atomicAdd(&g_count[dst[e]], 1);
}

// single block, 1024 threads: exclusive scan of g_count -> g_off/g_cur, inv_deg
__global__ void scan_kernel() {
    __shared__ int s[1024];
    const int t = threadIdx.x;
    const int CHUNK = (N_NODES + 1023) / 1024;  // 98
    int beg = t * CHUNK;
    int end = beg + CHUNK; if (end > N_NODES) end = N_NODES;
    if (beg > N_NODES) beg = N_NODES;
    int sum = 0;
    for (int i = beg; i < end; i++) sum += g_count[i];
    s[t] = sum;
    __syncthreads();
    for (int d = 1; d < 1024; d <<= 1) {
        int v = (t >= d) ? s[t - d] : 0;
        __syncthreads();
        s[t] += v;
        __syncthreads();
    }
    int run = (t > 0) ? s[t - 1] : 0;
    for (int i = beg; i < end; i++) {
        int c = g_count[i];
        g_off[i] = run;
        g_cur[i] = run;
        g_inv_deg[i] = 1.0f / (float)(c > 1 ? c : 1);
        run += c;
    }
    if (t == 1023) g_off[N_NODES] = s[1023];
}

__global__ void scatter_kernel(const int* __restrict__ src,
                               const int* __restrict__ dst) {
    int e = blockIdx.x * blockDim.x + threadIdx.x;
    if (e < N_EDGES) {
        int d = dst[e];
        int p = atomicAdd(&g_cur[d], 1);
        g_src_sorted[p] = src[e];
    }
}

// deterministic per-node neighbor order (makes fp sum order independent of
// scatter race outcome): tiny insertion sort, avg degree ~10
__global__ void sort_kernel() {
    int n = blockIdx.x * blockDim.x + threadIdx.x;
    if (n >= N_NODES) return;
    int beg = g_off[n], end = g_off[n + 1];
    for (int i = beg + 1; i < end; i++) {
        int key = g_src_sorted[i];
        int j = i - 1;
        while (j >= beg && g_src_sorted[j] > key) {
            g_src_sorted[j + 1] = g_src_sorted[j];
            j--;
        }
        g_src_sorted[j + 1] = key;
    }
}

// ---------------- mean-aggregation: one warp per dst node ----------------
template <int C>
__global__ void aggregate_kernel(const float* __restrict__ X, int ldx,
                                 float* __restrict__ OUT, int ldo) {
    int warp = (blockIdx.x * blockDim.x + threadIdx.x) >> 5;
    int lane = threadIdx.x & 31;
    if (warp >= N_NODES) return;
    int beg = g_off[warp], end = g_off[warp + 1];
    constexpr int V = (C + 31) / 32;
    float acc[V];
#pragma unroll
    for (int v = 0; v < V; v++) acc[v] = 0.0f;
    for (int i = beg; i < end; i++) {
        int s = g_src_sorted[i];
        const float* xr = X + (size_t)s * ldx;
#pragma unroll
        for (int v = 0; v < V; v++) {
            int col = lane + 32 * v;
            if (col < C) acc[v] += __ldg(xr + col);
        }
    }
    float inv = g_inv_deg[warp];
    float* orow = OUT + (size_t)warp * ldo;
#pragma unroll
    for (int v = 0; v < V; v++) {
        int col = lane + 32 * v;
        if (col < C) orow[col] = acc[v] * inv;
    }
}

// ---------------- fused dual-input GEMM: C = A1@W1 + A2@W2 + bias, relu ----
// row tile 128, 256 threads (16x16), each thread 8 rows x TN cols, M = 16*TN
template <int M, int TN>
__global__ void gemm_kernel(const float* __restrict__ A1, const float* __restrict__ W1, int K1,
                            const float* __restrict__ A2, const float* __restrict__ W2, int K2,
                            const float* __restrict__ bias, int do_relu,
                            float* __restrict__ C, int N) {
    constexpr int BR = 128, KT = 32;
    __shared__ float As[KT * (BR + 1)];
    __shared__ float Ws[KT * M];
    const int tid = threadIdx.x;
    const int tx = tid & 15, ty = tid >> 4;
    const int rowBase = blockIdx.x * BR;

    float acc[8][TN];
#pragma unroll
    for (int r = 0; r < 8; r++)
#pragma unroll
        for (int c = 0; c < TN; c++) acc[r][c] = 0.0f;

    for (int part = 0; part < 2; part++) {
        const float* A = (part == 0) ? A1 : A2;
        const float* W = (part == 0) ? W1 : W2;
        const int K = (part == 0) ? K1 : K2;
        if (K == 0) continue;
        for (int k0 = 0; k0 < K; k0 += KT) {
            __syncthreads();
            // A chunk: BR x KT, stored k-major with pad
#pragma unroll
            for (int i = 0; i < (BR * KT) / 256; i++) {
                int idx = tid + 256 * i;
                int row = idx >> 5;
                int kk  = idx & 31;
                int grow = rowBase + row;
                float v = (grow < N) ? A[(size_t)grow * K + k0 + kk] : 0.0f;
                As[kk * (BR + 1) + row] = v;
            }
            // W chunk: KT x M
            for (int idx = tid; idx < KT * M; idx += 256) {
                int kk = idx / M;
                int j  = idx - kk * M;
                Ws[kk * M + j] = W[(size_t)(k0 + kk) * M + j];
            }
            __syncthreads();
#pragma unroll
            for (int kk = 0; kk < KT; kk++) {
                float a[8], w[TN];
#pragma unroll
                for (int r = 0; r < 8; r++) a[r] = As[kk * (BR + 1) + ty + 16 * r];
#pragma unroll
                for (int c = 0; c < TN; c++) w[c] = Ws[kk * M + tx + 16 * c];
#pragma unroll
                for (int r = 0; r < 8; r++)
#pragma unroll
                    for (int c = 0; c < TN; c++) acc[r][c] += a[r] * w[c];
            }
        }
    }
#pragma unroll
    for (int r = 0; r < 8; r++) {
        int grow = rowBase + ty + 16 * r;
        if (grow < N) {
            float* crow = C + (size_t)grow * M;
#pragma unroll
            for (int c = 0; c < TN; c++) {
                int j = tx + 16 * c;
                float v = acc[r][c];
                if (bias) v += bias[j];
                if (do_relu) v = fmaxf(v, 0.0f);
                crow[j] = v;
            }
        }
    }
}

// ---------------- layer-3 weight concat: wcat[k, j] = j<40 ? w3_l : w3_r ----
__global__ void build_wcat_kernel(const float* __restrict__ w3l,
                                  const float* __restrict__ w3r) {
    int idx = blockIdx.x * blockDim.x + threadIdx.x;
    if (idx >= 128 * 80) return;
    int k = idx / 80, j = idx - k * 80;
    g_wcat[idx] = (j < 40) ? w3l[k * 40 + j] : w3r[k * 40 + (j - 40)];
}

// ---------------- final: add root path + bias, log_softmax (warp/row) -------
__global__ void final_kernel(const float* __restrict__ b3,
                             float* __restrict__ out) {
    int node = (blockIdx.x * blockDim.x + threadIdx.x) >> 5;
    int lane = threadIdx.x & 31;
    if (node >= N_NODES) return;
    const float* agg = g_agg + (size_t)node * 40;       // mean-agg of t[:, :40]
    const float* tr  = g_t   + (size_t)node * 80 + 40;  // root transform
    float v0 = agg[lane] + tr[lane] + b3[lane];
    float v1 = -INFINITY;
    if (lane < 8) v1 = agg[lane + 32] + tr[lane + 32] + b3[lane + 32];
    float m = fmaxf(v0, v1);
#pragma unroll
    for (int s = 16; s; s >>= 1) m = fmaxf(m, __shfl_xor_sync(0xFFFFFFFFu, m, s));
    float e = __expf(v0 - m) + ((lane < 8) ? __expf(v1 - m) : 0.0f);
#pragma unroll
    for (int s = 16; s; s >>= 1) e += __shfl_xor_sync(0xFFFFFFFFu, e, s);
    float lse = m + logf(e);
    float* orow = out + (size_t)node * 40;
    orow[lane] = v0 - lse;
    if (lane < 8) orow[lane + 32] = v1 - lse;
}

// ---------------- launch ----------------
extern "C" void kernel_launch(void* const* d_in, const int* in_sizes, int n_in,
                              void* d_out, int out_size) {
    const float* x    = (const float*)d_in[0];
    const int*   ei   = (const int*)d_in[1];   // [2, E] int32: row0=src, row1=dst
    const float* w1_l = (const float*)d_in[2];
    const float* w1_r = (const float*)d_in[3];
    const float* b1   = (const float*)d_in[4];
    const float* w2_l = (const float*)d_in[5];
    const float* w2_r = (const float*)d_in[6];
    const float* b2   = (const float*)d_in[7];
    const float* w3_l = (const float*)d_in[8];
    const float* w3_r = (const float*)d_in[9];
    const float* b3   = (const float*)d_in[10];
    float* out = (float*)d_out;

    const int* src = ei;
    const int* dst = ei + N_EDGES;

    float *agg, *h1, *h2, *t, *wcat;
    cudaGetSymbolAddress((void**)&agg,  g_agg);
    cudaGetSymbolAddress((void**)&h1,   g_h1);
    cudaGetSymbolAddress((void**)&h2,   g_h2);
    cudaGetSymbolAddress((void**)&t,    g_t);
    cudaGetSymbolAddress((void**)&wcat, g_wcat);

    const int TB = 256;
    const int nodeBlocks = (N_NODES + TB - 1) / TB;
    const int edgeBlocks = (N_EDGES + TB - 1) / TB;
    const int warpBlocks = (N_NODES * 32 + TB - 1) / TB;  // one warp per node
    const int gemmBlocks = (N_NODES + 127) / 128;

    // CSR build (once, reused by all 3 layers)
    zero_counts_kernel<<<nodeBlocks, TB>>>();
    hist_kernel<<<edgeBlocks, TB>>>(dst);
    scan_kernel<<<1, 1024>>>();
    scatter_kernel<<<edgeBlocks, TB>>>(src, dst);
    sort_kernel<<<nodeBlocks, TB>>>();

    // Layer 1: aggregate x (64-wide), then h1 = relu(agg@w1_l + x@w1_r + b1)
    aggregate_kernel<64><<<warpBlocks, TB>>>(x, 64, agg, 64);
    gemm_kernel<128, 8><<<gemmBlocks, TB>>>(agg, w1_l, 64, x, w1_r, 64, b1, 1, h1, N_NODES);

    // Layer 2: aggregate h1 (128-wide), h2 = relu(agg@w2_l + h1@w2_r + b2)
    aggregate_kernel<128><<<warpBlocks, TB>>>(h1, 128, agg, 128);
    gemm_kernel<128, 8><<<gemmBlocks, TB>>>(agg, w2_l, 128, h1, w2_r, 128, b2, 1, h2, N_NODES);

    // Layer 3: transform FIRST (linearity of mean-agg), aggregate only 40-wide
    build_wcat_kernel<<<(128 * 80 + TB - 1) / TB, TB>>>(w3_l, w3_r);
    gemm_kernel<80, 5><<<gemmBlocks, TB>>>(h2, wcat, 128, (const float*)0, (const float*)0, 0,
                                           (const float*)0, 0, t, N_NODES);
    aggregate_kernel<40><<<warpBlocks, TB>>>(t, 80, agg, 40);  // mean-agg of t[:, :40]
    final_kernel<<<warpBlocks, TB>>>(b3, out);
}

// round 4
// speedup vs baseline: 1.0923x; 1.0923x over previous
#include <cuda_runtime.h>
#include <cuda_bf16.h>
#include <math.h>

#define N_NODES 100000
#define N_EDGES 1000000

// ---------------- scratch (static device globals; no allocation) ----------------
__device__ int   g_count[N_NODES];
__device__ int   g_off[N_NODES + 1];
__device__ int   g_cur[N_NODES];
__device__ int   g_src_sorted[N_EDGES];
__device__ float g_inv_deg[N_NODES];
__device__ float g_agg[(size_t)N_NODES * 128];
__device__ float g_h1 [(size_t)N_NODES * 128];
__device__ float g_h2 [(size_t)N_NODES * 128];
__device__ float g_t  [(size_t)N_NODES * 80];
__device__ float g_wcat[128 * 80];

// ---------------- CSR construction ----------------
__global__ void zero_counts_kernel() {
    int i = blockIdx.x * blockDim.x + threadIdx.x;
    if (i < N_NODES) g_count[i] = 0;
}

__global__ void hist_kernel(const int* __restrict__ dst) {
    int e = blockIdx.x * blockDim.x + threadIdx.x;
    if (e < N_EDGES) atomicAdd(&g_count[dst[e]], 1);
}

// single block, 1024 threads: exclusive scan of g_count -> g_off/g_cur, inv_deg
__global__ void scan_kernel() {
    __shared__ int s[1024];
    const int t = threadIdx.x;
    const int CHUNK = (N_NODES + 1023) / 1024;  // 98
    int beg = t * CHUNK;
    int end = beg + CHUNK; if (end > N_NODES) end = N_NODES;
    if (beg > N_NODES) beg = N_NODES;
    int sum = 0;
    for (int i = beg; i < end; i++) sum += g_count[i];
    s[t] = sum;
    __syncthreads();
    for (int d = 1; d < 1024; d <<= 1) {
        int v = (t >= d) ? s[t - d] : 0;
        __syncthreads();
        s[t] += v;
        __syncthreads();
    }
    int run = (t > 0) ? s[t - 1] : 0;
    for (int i = beg; i < end; i++) {
        int c = g_count[i];
        g_off[i] = run;
        g_cur[i] = run;
        g_inv_deg[i] = 1.0f / (float)(c > 1 ? c : 1);
        run += c;
    }
    if (t == 1023) g_off[N_NODES] = s[1023];
}

__global__ void scatter_kernel(const int* __restrict__ src,
                               const int* __restrict__ dst) {
    int e = blockIdx.x * blockDim.x + threadIdx.x;
    if (e < N_EDGES) {
        int d = dst[e];
        int p = atomicAdd(&g_cur[d], 1);
        g_src_sorted[p] = src[e];
    }
}

// deterministic per-node neighbor order
__global__ void sort_kernel() {
    int n = blockIdx.x * blockDim.x + threadIdx.x;
    if (n >= N_NODES) return;
    int beg = g_off[n], end = g_off[n + 1];
    for (int i = beg + 1; i < end; i++) {
        int key = g_src_sorted[i];
        int j = i - 1;
        while (j >= beg && g_src_sorted[j] > key) {
            g_src_sorted[j + 1] = g_src_sorted[j];
            j--;
        }
        g_src_sorted[j + 1] = key;
    }
}

// ---------------- mean-aggregation: one warp per dst node ----------------
template <int C>
__global__ void aggregate_kernel(const float* __restrict__ X, int ldx,
                                 float* __restrict__ OUT, int ldo) {
    int warp = (blockIdx.x * blockDim.x + threadIdx.x) >> 5;
    int lane = threadIdx.x & 31;
    if (warp >= N_NODES) return;
    int beg = g_off[warp], end = g_off[warp + 1];
    constexpr int V = (C + 31) / 32;
    float acc[V];
#pragma unroll
    for (int v = 0; v < V; v++) acc[v] = 0.0f;
    for (int i = beg; i < end; i++) {
        int s = g_src_sorted[i];
        const float* xr = X + (size_t)s * ldx;
#pragma unroll
        for (int v = 0; v < V; v++) {
            int col = lane + 32 * v;
            if (col < C) acc[v] += __ldg(xr + col);
        }
    }
    float inv = g_inv_deg[warp];
    float* orow = OUT + (size_t)warp * ldo;
#pragma unroll
    for (int v = 0; v < V; v++) {
        int col = lane + 32 * v;
        if (col < C) orow[col] = acc[v] * inv;
    }
}

// ---------------- tf32 helpers ----------------
__device__ __forceinline__ unsigned f2tf32(float f) {
    unsigned r;
    asm("cvt.rna.tf32.f32 %0, %1;" : "=r"(r) : "f"(f));
    return r;
}

__device__ __forceinline__ void mma_tf32(float* c, const unsigned* a, const unsigned* b) {
    asm volatile(
        "mma.sync.aligned.m16n8k8.row.col.f32.tf32.tf32.f32 "
        "{%0,%1,%2,%3}, {%4,%5,%6,%7}, {%8,%9}, {%0,%1,%2,%3};\n"
        : "+f"(c[0]), "+f"(c[1]), "+f"(c[2]), "+f"(c[3])
        : "r"(a[0]), "r"(a[1]), "r"(a[2]), "r"(a[3]),
          "r"(b[0]), "r"(b[1]));
}

// ---------------- tensor-core dual-input GEMM: C = A1@W1 + A2@W2 + bias, relu ----
// BM=128 rows, 8 warps (16 rows/warp), each warp computes all N cols.
// N must be a multiple of 8; K1/K2 multiples of 16.
template <int N>
__global__ void __launch_bounds__(256)
gemm_tc_kernel(const float* __restrict__ A1, const float* __restrict__ W1, int K1,
               const float* __restrict__ A2, const float* __restrict__ W2, int K2,
               const float* __restrict__ bias, int do_relu,
               float* __restrict__ C, int Nrows) {
    constexpr int BM = 128, BK = 16, BKP = BK + 1;
    constexpr int NT = N / 8;                 // n-tiles per warp
    __shared__ unsigned As[BM * BKP];         // tf32 bits, row-major [BM][BKP]
    __shared__ unsigned Ws[BK * N];           // tf32 bits, [BK][N]

    const int tid  = threadIdx.x;
    const int warp = tid >> 5;
    const int lane = tid & 31;
    const int g = lane >> 2;                  // group id 0..7
    const int cq = lane & 3;                  // thread-in-group 0..3
    const int rowBase = blockIdx.x * BM;

    float acc[NT][4];
#pragma unroll
    for (int nt = 0; nt < NT; nt++)
#pragma unroll
        for (int i = 0; i < 4; i++) acc[nt][i] = 0.0f;

    for (int part = 0; part < 2; part++) {
        const float* A = (part == 0) ? A1 : A2;
        const float* W = (part == 0) ? W1 : W2;
        const int K = (part == 0) ? K1 : K2;
        if (K == 0) continue;
        for (int k0 = 0; k0 < K; k0 += BK) {
            __syncthreads();
            // stage A tile: BM x BK fp32 -> tf32
#pragma unroll
            for (int i = 0; i < (BM * BK) / 256; i++) {
                int idx = tid + 256 * i;
                int row = idx >> 4;           // /BK
                int kk  = idx & 15;
                int grow = rowBase + row;
                float v = (grow < Nrows) ? A[(size_t)grow * K + k0 + kk] : 0.0f;
                As[row * BKP + kk] = f2tf32(v);
            }
            // stage W tile: BK x N
            for (int idx = tid; idx < BK * N; idx += 256) {
                int kk = idx / N;
                int j  = idx - kk * N;
                Ws[idx] = f2tf32(W[(size_t)(k0 + kk) * N + j]);
            }
            __syncthreads();
#pragma unroll
            for (int ks = 0; ks < BK; ks += 8) {
                unsigned a[4];
                const int r0 = (warp * 16 + g) * BKP + ks + cq;
                a[0] = As[r0];
                a[1] = As[r0 + 8 * BKP];
                a[2] = As[r0 + 4];
                a[3] = As[r0 + 8 * BKP + 4];
#pragma unroll
                for (int nt = 0; nt < NT; nt++) {
                    unsigned b[2];
                    b[0] = Ws[(ks + cq) * N + nt * 8 + g];
                    b[1] = Ws[(ks + cq + 4) * N + nt * 8 + g];
                    mma_tf32(acc[nt], a, b);
                }
            }
        }
    }
    // epilogue: thread owns (row, col) = (warpRow + g [+8], nt*8 + 2*cq [+1])
    const int row0 = rowBase + warp * 16 + g;
#pragma unroll
    for (int nt = 0; nt < NT; nt++) {
        int col = nt * 8 + 2 * cq;
        float v0 = acc[nt][0], v1 = acc[nt][1], v2 = acc[nt][2], v3 = acc[nt][3];
        if (bias) {
            float bc0 = bias[col], bc1 = bias[col + 1];
            v0 += bc0; v1 += bc1; v2 += bc0; v3 += bc1;
        }
        if (do_relu) {
            v0 = fmaxf(v0, 0.0f); v1 = fmaxf(v1, 0.0f);
            v2 = fmaxf(v2, 0.0f); v3 = fmaxf(v3, 0.0f);
        }
        if (row0 < Nrows) {
            C[(size_t)row0 * N + col]     = v0;
            C[(size_t)row0 * N + col + 1] = v1;
        }
        if (row0 + 8 < Nrows) {
            C[(size_t)(row0 + 8) * N + col]     = v2;
            C[(size_t)(row0 + 8) * N + col + 1] = v3;
        }
    }
}

// ---------------- layer-3 weight concat: wcat[k, j] = j<40 ? w3_l : w3_r ----
__global__ void build_wcat_kernel(const float* __restrict__ w3l,
                                  const float* __restrict__ w3r) {
    int idx = blockIdx.x * blockDim.x + threadIdx.x;
    if (idx >= 128 * 80) return;
    int k = idx / 80, j = idx - k * 80;
    g_wcat[idx] = (j < 40) ? w3l[k * 40 + j] : w3r[k * 40 + (j - 40)];
}

// ---------------- final: add root path + bias, log_softmax (warp/row) -------
__global__ void final_kernel(const float* __restrict__ b3,
                             float* __restrict__ out) {
    int node = (blockIdx.x * blockDim.x + threadIdx.x) >> 5;
    int lane = threadIdx.x & 31;
    if (node >= N_NODES) return;
    const float* agg = g_agg + (size_t)node * 40;       // mean-agg of t[:, :40]
    const float* tr  = g_t   + (size_t)node * 80 + 40;  // root transform
    float v0 = agg[lane] + tr[lane] + b3[lane];
    float v1 = -INFINITY;
    if (lane < 8) v1 = agg[lane + 32] + tr[lane + 32] + b3[lane + 32];
    float m = fmaxf(v0, v1);
#pragma unroll
    for (int s = 16; s; s >>= 1) m = fmaxf(m, __shfl_xor_sync(0xFFFFFFFFu, m, s));
    float e = __expf(v0 - m) + ((lane < 8) ? __expf(v1 - m) : 0.0f);
#pragma unroll
    for (int s = 16; s; s >>= 1) e += __shfl_xor_sync(0xFFFFFFFFu, e, s);
    float lse = m + logf(e);
    float* orow = out + (size_t)node * 40;
    orow[lane] = v0 - lse;
    if (lane < 8) orow[lane + 32] = v1 - lse;
}

// ---------------- launch ----------------
extern "C" void kernel_launch(void* const* d_in, const int* in_sizes, int n_in,
                              void* d_out, int out_size) {
    const float* x    = (const float*)d_in[0];
    const int*   ei   = (const int*)d_in[1];   // [2, E] int32: row0=src, row1=dst
    const float* w1_l = (const float*)d_in[2];
    const float* w1_r = (const float*)d_in[3];
    const float* b1   = (const float*)d_in[4];
    const float* w2_l = (const float*)d_in[5];
    const float* w2_r = (const float*)d_in[6];
    const float* b2   = (const float*)d_in[7];
    const float* w3_l = (const float*)d_in[8];
    const float* w3_r = (const float*)d_in[9];
    const float* b3   = (const float*)d_in[10];
    float* out = (float*)d_out;

    const int* src = ei;
    const int* dst = ei + N_EDGES;

    float *agg, *h1, *h2, *t, *wcat;
    cudaGetSymbolAddress((void**)&agg,  g_agg);
    cudaGetSymbolAddress((void**)&h1,   g_h1);
    cudaGetSymbolAddress((void**)&h2,   g_h2);
    cudaGetSymbolAddress((void**)&t,    g_t);
    cudaGetSymbolAddress((void**)&wcat, g_wcat);

    const int TB = 256;
    const int nodeBlocks = (N_NODES + TB - 1) / TB;
    const int edgeBlocks = (N_EDGES + TB - 1) / TB;
    const int warpBlocks = (N_NODES * 32 + TB - 1) / TB;  // one warp per node
    const int gemmBlocks = (N_NODES + 127) / 128;

    // CSR build (once, reused by all 3 layers)
    zero_counts_kernel<<<nodeBlocks, TB>>>();
    hist_kernel<<<edgeBlocks, TB>>>(dst);
    scan_kernel<<<1, 1024>>>();
    scatter_kernel<<<edgeBlocks, TB>>>(src, dst);
    sort_kernel<<<nodeBlocks, TB>>>();

    // Layer 1: aggregate x (64-wide), then h1 = relu(agg@w1_l + x@w1_r + b1)
    aggregate_kernel<64><<<warpBlocks, TB>>>(x, 64, agg, 64);
    gemm_tc_kernel<128><<<gemmBlocks, TB>>>(agg, w1_l, 64, x, w1_r, 64, b1, 1, h1, N_NODES);

    // Layer 2: aggregate h1 (128-wide), h2 = relu(agg@w2_l + h1@w2_r + b2)
    aggregate_kernel<128><<<warpBlocks, TB>>>(h1, 128, agg, 128);
    gemm_tc_kernel<128><<<gemmBlocks, TB>>>(agg, w2_l, 128, h1, w2_r, 128, b2, 1, h2, N_NODES);

    // Layer 3: transform FIRST (linearity of mean-agg), aggregate only 40-wide
    build_wcat_kernel<<<(128 * 80 + TB - 1) / TB, TB>>>(w3_l, w3_r);
    gemm_tc_kernel<80><<<gemmBlocks, TB>>>(h2, wcat, 128, (const float*)0, (const float*)0, 0,
                                           (const float*)0, 0, t, N_NODES);
    aggregate_kernel<40><<<warpBlocks, TB>>>(t, 80, agg, 40);  // mean-agg of t[:, :40]
    final_kernel<<<warpBlocks, TB>>>(b3, out);
}

// round 5
// speedup vs baseline: 1.3679x; 1.2522x over previous
#include <cuda_runtime.h>
#include <cuda_fp16.h>
#include <math.h>

#define N_NODES 100000
#define N_EDGES 1000000

// ---------------- scratch (static device globals; no allocation) ----------------
__device__ int    g_count[N_NODES];
__device__ int    g_off[N_NODES + 1];
__device__ int    g_cur[N_NODES];
__device__ int    g_src_sorted[N_EDGES];
__device__ float  g_inv_deg[N_NODES];
__device__ __half g_xh [(size_t)N_NODES * 64];
__device__ __half g_agg[(size_t)N_NODES * 128];
__device__ __half g_h1 [(size_t)N_NODES * 128];
__device__ __half g_h2 [(size_t)N_NODES * 128];
__device__ float  g_t  [(size_t)N_NODES * 80];
__device__ float  g_wcat[128 * 80];

// ---------------- hist + x->fp16 convert (fused) ----------------
__global__ void hist_conv_kernel(const int* __restrict__ dst,
                                 const float* __restrict__ x) {
    int i = blockIdx.x * blockDim.x + threadIdx.x;
    if (i < N_EDGES) atomicAdd(&g_count[dst[i]], 1);
    int base = i * 4;
    if (base < N_NODES * 64) {
        float4 v = *(const float4*)(x + base);
        __half2 p0 = __floats2half2_rn(v.x, v.y);
        __half2 p1 = __floats2half2_rn(v.z, v.w);
        uint2 pk;
        pk.x = *(unsigned*)&p0;
        pk.y = *(unsigned*)&p1;
        *(uint2*)(g_xh + base) = pk;
    }
}

// single block, 1024 threads: exclusive scan of g_count -> g_off/g_cur, inv_deg.
// Also re-zeros g_count for the next graph replay (module init zeros it first).
__global__ void scan_kernel() {
    __shared__ int s[1024];
    const int t = threadIdx.x;
    const int CHUNK = (N_NODES + 1023) / 1024;  // 98
    int beg = t * CHUNK;
    int end = beg + CHUNK; if (end > N_NODES) end = N_NODES;
    if (beg > N_NODES) beg = N_NODES;
    int sum = 0;
    for (int i = beg; i < end; i++) sum += g_count[i];
    s[t] = sum;
    __syncthreads();
    for (int d = 1; d < 1024; d <<= 1) {
        int v = (t >= d) ? s[t - d] : 0;
        __syncthreads();
        s[t] += v;
        __syncthreads();
    }
    int run = (t > 0) ? s[t - 1] : 0;
    for (int i = beg; i < end; i++) {
        int c = g_count[i];
        g_count[i] = 0;                         // re-zero for next replay
        g_off[i] = run;
        g_cur[i] = run;
        g_inv_deg[i] = 1.0f / (float)(c > 1 ? c : 1);
        run += c;
    }
    if (t == 1023) g_off[N_NODES] = s[1023];
}

__global__ void scatter_kernel(const int* __restrict__ src,
                               const int* __restrict__ dst) {
    int e = blockIdx.x * blockDim.x + threadIdx.x;
    if (e < N_EDGES) {
        int d = dst[e];
        int p = atomicAdd(&g_cur[d], 1);
        g_src_sorted[p] = src[e];
    }
}

// deterministic per-node neighbor order (sorted by src value)
__global__ void sort_kernel() {
    int n = blockIdx.x * blockDim.x + threadIdx.x;
    if (n >= N_NODES) return;
    int beg = g_off[n], end = g_off[n + 1];
    for (int i = beg + 1; i < end; i++) {
        int key = g_src_sorted[i];
        int j = i - 1;
        while (j >= beg && g_src_sorted[j] > key) {
            g_src_sorted[j + 1] = g_src_sorted[j];
            j--;
        }
        g_src_sorted[j + 1] = key;
    }
}

// ---------------- mean-aggregation (fp16 rows): one warp per dst node ----------
// CH halves per row; lane owns 4 halves (uint2) at col 4*lane (active if 4*lane<CH).
template <int CH>
__global__ void aggregate_h_kernel(const __half* __restrict__ X,
                                   __half* __restrict__ OUT) {
    int node = (blockIdx.x * blockDim.x + threadIdx.x) >> 5;
    int lane = threadIdx.x & 31;
    if (node >= N_NODES) return;
    const bool act = (4 * lane < CH);
    int beg = g_off[node], end = g_off[node + 1];
    float a0 = 0.f, a1 = 0.f, a2 = 0.f, a3 = 0.f;
    int i = beg;
    for (; i + 1 < end; i += 2) {
        int s0 = __ldg(g_src_sorted + i);
        int s1 = __ldg(g_src_sorted + i + 1);
        if (act) {
            uint2 v0 = *(const uint2*)(X + (size_t)s0 * CH + 4 * lane);
            uint2 v1 = *(const uint2*)(X + (size_t)s1 * CH + 4 * lane);
            float2 f;
            f = __half22float2(*(__half2*)&v0.x); a0 += f.x; a1 += f.y;
            f = __half22float2(*(__half2*)&v0.y); a2 += f.x; a3 += f.y;
            f = __half22float2(*(__half2*)&v1.x); a0 += f.x; a1 += f.y;
            f = __half22float2(*(__half2*)&v1.y); a2 += f.x; a3 += f.y;
        }
    }
    if (i < end) {
        int s0 = __ldg(g_src_sorted + i);
        if (act) {
            uint2 v0 = *(const uint2*)(X + (size_t)s0 * CH + 4 * lane);
            float2 f;
            f = __half22float2(*(__half2*)&v0.x); a0 += f.x; a1 += f.y;
            f = __half22float2(*(__half2*)&v0.y); a2 += f.x; a3 += f.y;
        }
    }
    if (act) {
        float inv = g_inv_deg[node];
        __half2 p0 = __floats2half2_rn(a0 * inv, a1 * inv);
        __half2 p1 = __floats2half2_rn(a2 * inv, a3 * inv);
        uint2 pk;
        pk.x = *(unsigned*)&p0;
        pk.y = *(unsigned*)&p1;
        *(uint2*)(OUT + (size_t)node * CH + 4 * lane) = pk;
    }
}

// ---------------- fp16 tensor-core dual-input GEMM ----------------
// C = A1@W1 + A2@W2 + bias, optional relu. A inputs fp16, W fp32 (converted in
// staging), accumulate fp32, output type CT (float or __half).
// BM=128 rows/CTA, 8 warps (16 rows each), each warp computes all N cols.
// SMEM: As [128 rows][24 halves] (stride 12 words: banks {12g+cq} conflict-free)
//       Wt [N rows][24 halves]   (transposed W, same stride)
__device__ __forceinline__ void mma_f16(float* c, const unsigned* a, const unsigned* b) {
    asm volatile(
        "mma.sync.aligned.m16n8k16.row.col.f32.f16.f16.f32 "
        "{%0,%1,%2,%3}, {%4,%5,%6,%7}, {%8,%9}, {%0,%1,%2,%3};\n"
        : "+f"(c[0]), "+f"(c[1]), "+f"(c[2]), "+f"(c[3])
        : "r"(a[0]), "r"(a[1]), "r"(a[2]), "r"(a[3]),
          "r"(b[0]), "r"(b[1]));
}

template <int N, typename CT>
__global__ void __launch_bounds__(256)
gemm_h_kernel(const __half* __restrict__ A1, const float* __restrict__ W1, int K1,
              const __half* __restrict__ A2, const float* __restrict__ W2, int K2,
              const float* __restrict__ bias, int do_relu,
              CT* __restrict__ C, int Nrows) {
    constexpr int BM = 128, BK = 16, RS = 24;   // RS = smem row stride in halves
    constexpr int NT = N / 8;
    __shared__ __align__(16) __half As[BM * RS];
    __shared__ __align__(16) __half Wt[N * RS];

    const int tid  = threadIdx.x;
    const int warp = tid >> 5;
    const int lane = tid & 31;
    const int g  = lane >> 2;
    const int cq = lane & 3;
    const int rowBase = blockIdx.x * BM;

    float acc[NT][4];
#pragma unroll
    for (int nt = 0; nt < NT; nt++)
#pragma unroll
        for (int i = 0; i < 4; i++) acc[nt][i] = 0.0f;

    for (int part = 0; part < 2; part++) {
        const __half* A = (part == 0) ? A1 : A2;
        const float*  W = (part == 0) ? W1 : W2;
        const int K = (part == 0) ? K1 : K2;
        if (K == 0) continue;
        for (int k0 = 0; k0 < K; k0 += BK) {
            __syncthreads();
            // stage A: 128x16 halves; one uint4 (8 halves) per thread
            {
                int row = tid >> 1;
                int hc  = (tid & 1) * 8;
                int grow = rowBase + row;
                uint4 v = make_uint4(0, 0, 0, 0);
                if (grow < Nrows)
                    v = *(const uint4*)(A + (size_t)grow * K + k0 + hc);
                *(uint4*)(As + row * RS + hc) = v;
            }
            // stage W transposed: Wt[j][kk] = half(W[k0+kk][j])
            for (int idx = tid; idx < BK * N; idx += 256) {
                int kk = idx / N;
                int j  = idx - kk * N;
                Wt[j * RS + kk] = __float2half_rn(W[(size_t)(k0 + kk) * N + j]);
            }
            __syncthreads();
            // one m16n8k16 step consumes the whole BK=16 tile
            unsigned a[4];
            const int r0 = (warp * 16 + g) * RS + 2 * cq;
            a[0] = *(const unsigned*)(As + r0);
            a[1] = *(const unsigned*)(As + r0 + 8 * RS);
            a[2] = *(const unsigned*)(As + r0 + 8);
            a[3] = *(const unsigned*)(As + r0 + 8 * RS + 8);
#pragma unroll
            for (int nt = 0; nt < NT; nt++) {
                unsigned b[2];
                const int wr = (nt * 8 + g) * RS + 2 * cq;
                b[0] = *(const unsigned*)(Wt + wr);
                b[1] = *(const unsigned*)(Wt + wr + 8);
                mma_f16(acc[nt], a, b);
            }
        }
    }
    // epilogue: thread owns (row, col) = (warpRow + g [+8], nt*8 + 2cq [+1])
    const int row0 = rowBase + warp * 16 + g;
#pragma unroll
    for (int nt = 0; nt < NT; nt++) {
        int col = nt * 8 + 2 * cq;
        float v0 = acc[nt][0], v1 = acc[nt][1], v2 = acc[nt][2], v3 = acc[nt][3];
        if (bias) {
            float bc0 = bias[col], bc1 = bias[col + 1];
            v0 += bc0; v1 += bc1; v2 += bc0; v3 += bc1;
        }
        if (do_relu) {
            v0 = fmaxf(v0, 0.0f); v1 = fmaxf(v1, 0.0f);
            v2 = fmaxf(v2, 0.0f); v3 = fmaxf(v3, 0.0f);
        }
        if (row0 < Nrows) {
            CT* p = C + (size_t)row0 * N + col;
            if (sizeof(CT) == 2) {
                __half2 h = __floats2half2_rn(v0, v1);
                *(unsigned*)p = *(unsigned*)&h;
            } else {
                ((float*)p)[0] = v0; ((float*)p)[1] = v1;
            }
        }
        if (row0 + 8 < Nrows) {
            CT* p = C + (size_t)(row0 + 8) * N + col;
            if (sizeof(CT) == 2) {
                __half2 h = __floats2half2_rn(v2, v3);
                *(unsigned*)p = *(unsigned*)&h;
            } else {
                ((float*)p)[0] = v2; ((float*)p)[1] = v3;
            }
        }
    }
}

// ---------------- layer-3 weight concat: wcat[k, j] = j<40 ? w3_l : w3_r ----
__global__ void build_wcat_kernel(const float* __restrict__ w3l,
                                  const float* __restrict__ w3r) {
    int idx = blockIdx.x * blockDim.x + threadIdx.x;
    if (idx >= 128 * 80) return;
    int k = idx / 80, j = idx - k * 80;
    g_wcat[idx] = (j < 40) ? w3l[k * 40 + j] : w3r[k * 40 + (j - 40)];
}

// ---------------- fused: mean-agg of t[:, :40] + root + bias + log_softmax ----
__global__ void final_kernel(const float* __restrict__ b3,
                             float* __restrict__ out) {
    int node = (blockIdx.x * blockDim.x + threadIdx.x) >> 5;
    int lane = threadIdx.x & 31;
    if (node >= N_NODES) return;
    int beg = g_off[node], end = g_off[node + 1];
    float a0 = 0.f, a1 = 0.f;
    int i = beg;
    for (; i + 1 < end; i += 2) {
        int s0 = __ldg(g_src_sorted + i);
        int s1 = __ldg(g_src_sorted + i + 1);
        const float* r0 = g_t + (size_t)s0 * 80;
        const float* r1 = g_t + (size_t)s1 * 80;
        a0 += __ldg(r0 + lane) + __ldg(r1 + lane);
        if (lane < 8) a1 += __ldg(r0 + 32 + lane) + __ldg(r1 + 32 + lane);
    }
    if (i < end) {
        int s0 = __ldg(g_src_sorted + i);
        const float* r0 = g_t + (size_t)s0 * 80;
        a0 += __ldg(r0 + lane);
        if (lane < 8) a1 += __ldg(r0 + 32 + lane);
    }
    float inv = g_inv_deg[node];
    const float* tr = g_t + (size_t)node * 80 + 40;   // root transform
    float v0 = a0 * inv + tr[lane] + b3[lane];
    float v1 = -INFINITY;
    if (lane < 8) v1 = a1 * inv + tr[32 + lane] + b3[32 + lane];
    float m = fmaxf(v0, v1);
#pragma unroll
    for (int s = 16; s; s >>= 1) m = fmaxf(m, __shfl_xor_sync(0xFFFFFFFFu, m, s));
    float e = __expf(v0 - m) + ((lane < 8) ? __expf(v1 - m) : 0.0f);
#pragma unroll
    for (int s = 16; s; s >>= 1) e += __shfl_xor_sync(0xFFFFFFFFu, e, s);
    float lse = m + logf(e);
    float* orow = out + (size_t)node * 40;
    orow[lane] = v0 - lse;
    if (lane < 8) orow[lane + 32] = v1 - lse;
}

// ---------------- launch ----------------
extern "C" void kernel_launch(void* const* d_in, const int* in_sizes, int n_in,
                              void* d_out, int out_size) {
    const float* x    = (const float*)d_in[0];
    const int*   ei   = (const int*)d_in[1];   // [2, E] int32: row0=src, row1=dst
    const float* w1_l = (const float*)d_in[2];
    const float* w1_r = (const float*)d_in[3];
    const float* b1   = (const float*)d_in[4];
    const float* w2_l = (const float*)d_in[5];
    const float* w2_r = (const float*)d_in[6];
    const float* b2   = (const float*)d_in[7];
    const float* w3_l = (const float*)d_in[8];
    const float* w3_r = (const float*)d_in[9];
    const float* b3   = (const float*)d_in[10];
    float* out = (float*)d_out;

    const int* src = ei;
    const int* dst = ei + N_EDGES;

    __half *xh, *agg, *h1, *h2;
    float *t, *wcat;
    cudaGetSymbolAddress((void**)&xh,   g_xh);
    cudaGetSymbolAddress((void**)&agg,  g_agg);
    cudaGetSymbolAddress((void**)&h1,   g_h1);
    cudaGetSymbolAddress((void**)&h2,   g_h2);
    cudaGetSymbolAddress((void**)&t,    g_t);
    cudaGetSymbolAddress((void**)&wcat, g_wcat);

    const int TB = 256;
    const int nodeBlocks = (N_NODES + TB - 1) / TB;
    const int convThreads = (N_NODES * 64) / 4;                 // 1.6M
    const int histBlocks = (convThreads + TB - 1) / TB;         // covers edges too
    const int warpBlocks = (N_NODES * 32 + TB - 1) / TB;        // one warp per node
    const int gemmBlocks = (N_NODES + 127) / 128;

    // CSR build + x->fp16 (g_count re-zeroed inside scan for graph replay)
    hist_conv_kernel<<<histBlocks, TB>>>(dst, x);
    scan_kernel<<<1, 1024>>>();
    scatter_kernel<<<(N_EDGES + TB - 1) / TB, TB>>>(src, dst);
    sort_kernel<<<nodeBlocks, TB>>>();
    build_wcat_kernel<<<(128 * 80 + TB - 1) / TB, TB>>>(w3_l, w3_r);

    // Layer 1: aggregate xh (64), h1 = relu(agg@w1_l + xh@w1_r + b1)  [fp16 out]
    aggregate_h_kernel<64><<<warpBlocks, TB>>>(xh, agg);
    gemm_h_kernel<128, __half><<<gemmBlocks, TB>>>(agg, w1_l, 64, xh, w1_r, 64,
                                                   b1, 1, h1, N_NODES);

    // Layer 2: aggregate h1 (128), h2 = relu(agg@w2_l + h1@w2_r + b2)  [fp16 out]
    aggregate_h_kernel<128><<<warpBlocks, TB>>>(h1, agg);
    gemm_h_kernel<128, __half><<<gemmBlocks, TB>>>(agg, w2_l, 128, h1, w2_r, 128,
                                                   b2, 1, h2, N_NODES);

    // Layer 3: transform FIRST (linearity), t = h2 @ wcat  [fp32 out, 80 wide]
    gemm_h_kernel<80, float><<<gemmBlocks, TB>>>(h2, wcat, 128,
                                                 (const __half*)0, (const float*)0, 0,
                                                 (const float*)0, 0, t, N_NODES);
    // fused: mean-agg of t[:, :40] + root t[:, 40:] + b3 + log_softmax
    final_kernel<<<warpBlocks, TB>>>(b3, out);
}

// round 6
// speedup vs baseline: 2.5964x; 1.8981x over previous
#include <cuda_runtime.h>
#include <cuda_fp16.h>
#include <math.h>

#define N_NODES 100000
#define N_EDGES 1000000
#define SCAN_NB 98   // ceil(100000/1024)

// ---------------- scratch (static device globals; no allocation) ----------------
__device__ int    g_count[N_NODES];
__device__ int    g_off[N_NODES + 1];
__device__ int    g_cur[N_NODES];
__device__ int    g_bsum[128];
__device__ int    g_src_sorted[N_EDGES];
__device__ float  g_inv_deg[N_NODES];
__device__ __half g_xh [(size_t)N_NODES * 64];
__device__ __half g_agg[(size_t)N_NODES * 128];
__device__ __half g_h1 [(size_t)N_NODES * 128];
__device__ __half g_h2 [(size_t)N_NODES * 128];
__device__ float  g_t  [(size_t)N_NODES * 80];
__device__ float  g_wcat[128 * 80];

// ---------------- hist + x->fp16 convert (fused) ----------------
__global__ void hist_conv_kernel(const int* __restrict__ dst,
                                 const float* __restrict__ x) {
    int i = blockIdx.x * blockDim.x + threadIdx.x;
    if (i < N_EDGES) atomicAdd(&g_count[dst[i]], 1);
    int base = i * 4;
    if (base < N_NODES * 64) {
        float4 v = *(const float4*)(x + base);
        __half2 p0 = __floats2half2_rn(v.x, v.y);
        __half2 p1 = __floats2half2_rn(v.z, v.w);
        uint2 pk;
        pk.x = *(unsigned*)&p0;
        pk.y = *(unsigned*)&p1;
        *(uint2*)(g_xh + base) = pk;
    }
}

// ---------------- 3-phase coalesced scan ----------------
// Phase A: per-block (1024-wide) exclusive scan of g_count into g_off, block sums
__global__ void scanA_kernel() {
    __shared__ int s[1024];
    const int t = threadIdx.x;
    const int i = blockIdx.x * 1024 + t;
    int c = (i < N_NODES) ? g_count[i] : 0;
    s[t] = c;
    __syncthreads();
    for (int d = 1; d < 1024; d <<= 1) {
        int v = (t >= d) ? s[t - d] : 0;
        __syncthreads();
        s[t] += v;
        __syncthreads();
    }
    if (i < N_NODES) g_off[i] = s[t] - c;      // exclusive within block
    if (t == 1023) g_bsum[blockIdx.x] = s[1023];
}

// Phase C: each block inlines the (tiny) scan of block sums, then finalizes
// g_off/g_cur/g_inv_deg and re-zeros g_count for the next graph replay.
__global__ void scanC_kernel() {
    __shared__ int bs[SCAN_NB];
    const int t = threadIdx.x;
    if (t < SCAN_NB) bs[t] = g_bsum[t];
    __syncthreads();
    if (t == 0) {
        int run = 0;
        for (int b = 0; b < SCAN_NB; b++) { int c = bs[b]; bs[b] = run; run += c; }
        if (blockIdx.x == 0) g_off[N_NODES] = run;
    }
    __syncthreads();
    int i = blockIdx.x * 1024 + t;
    if (i < N_NODES) {
        int off = g_off[i] + bs[blockIdx.x];
        int c = g_count[i];
        g_off[i] = off;
        g_cur[i] = off;
        g_inv_deg[i] = 1.0f / (float)(c > 1 ? c : 1);
        g_count[i] = 0;                         // re-zero for next replay
    }
}

__global__ void scatter_kernel(const int* __restrict__ src,
                               const int* __restrict__ dst) {
    int e = blockIdx.x * blockDim.x + threadIdx.x;
    if (e < N_EDGES) {
        int d = dst[e];
        int p = atomicAdd(&g_cur[d], 1);
        g_src_sorted[p] = src[e];
    }
}

// ---------------- deterministic neighbor order: warp bitonic sort ----------------
// One warp per node. deg<=32: in-register bitonic via shfl (15 steps).
// deg>32 (vanishingly rare for Poisson(10)): lane-0 insertion sort fallback.
__global__ void sort_kernel() {
    int node = (blockIdx.x * blockDim.x + threadIdx.x) >> 5;
    int lane = threadIdx.x & 31;
    if (node >= N_NODES) return;
    int beg = g_off[node], end = g_off[node + 1];
    int deg = end - beg;
    if (deg <= 1) return;
    if (deg <= 32) {
        int v = (lane < deg) ? g_src_sorted[beg + lane] : 0x7FFFFFFF;
#pragma unroll
        for (int k = 2; k <= 32; k <<= 1) {
#pragma unroll
            for (int j = k >> 1; j; j >>= 1) {
                int o = __shfl_xor_sync(0xFFFFFFFFu, v, j);
                bool up    = ((lane & k) == 0);
                bool lower = ((lane & j) == 0);   // lane < partner
                v = (up == lower) ? min(v, o) : max(v, o);
            }
        }
        if (lane < deg) g_src_sorted[beg + lane] = v;
    } else if (lane == 0) {
        for (int i = beg + 1; i < end; i++) {
            int key = g_src_sorted[i];
            int j = i - 1;
            while (j >= beg && g_src_sorted[j] > key) {
                g_src_sorted[j + 1] = g_src_sorted[j];
                j--;
            }
            g_src_sorted[j + 1] = key;
        }
    }
}

// ---------------- mean-aggregation (fp16 rows): one warp per dst node ----------
// High-MLP: indices loaded lane-parallel then shfl-broadcast; row gathers 4-deep.
template <int CH>
__global__ void aggregate_h_kernel(const __half* __restrict__ X,
                                   __half* __restrict__ OUT) {
    int node = (blockIdx.x * blockDim.x + threadIdx.x) >> 5;
    int lane = threadIdx.x & 31;
    if (node >= N_NODES) return;
    const bool act = (4 * lane < CH);
    const int col = 4 * lane;
    int beg = g_off[node], end = g_off[node + 1];
    float a0 = 0.f, a1 = 0.f, a2 = 0.f, a3 = 0.f;
    for (int c = beg; c < end; c += 32) {
        int m = end - c; if (m > 32) m = 32;
        int sidx = (lane < m) ? __ldg(g_src_sorted + c + lane) : 0;
        int i = 0;
        for (; i + 4 <= m; i += 4) {
            int s0 = __shfl_sync(0xFFFFFFFFu, sidx, i);
            int s1 = __shfl_sync(0xFFFFFFFFu, sidx, i + 1);
            int s2 = __shfl_sync(0xFFFFFFFFu, sidx, i + 2);
            int s3 = __shfl_sync(0xFFFFFFFFu, sidx, i + 3);
            if (act) {
                uint2 v0 = *(const uint2*)(X + (size_t)s0 * CH + col);
                uint2 v1 = *(const uint2*)(X + (size_t)s1 * CH + col);
                uint2 v2 = *(const uint2*)(X + (size_t)s2 * CH + col);
                uint2 v3 = *(const uint2*)(X + (size_t)s3 * CH + col);
                float2 f;
                f = __half22float2(*(__half2*)&v0.x); a0 += f.x; a1 += f.y;
                f = __half22float2(*(__half2*)&v0.y); a2 += f.x; a3 += f.y;
                f = __half22float2(*(__half2*)&v1.x); a0 += f.x; a1 += f.y;
                f = __half22float2(*(__half2*)&v1.y); a2 += f.x; a3 += f.y;
                f = __half22float2(*(__half2*)&v2.x); a0 += f.x; a1 += f.y;
                f = __half22float2(*(__half2*)&v2.y); a2 += f.x; a3 += f.y;
                f = __half22float2(*(__half2*)&v3.x); a0 += f.x; a1 += f.y;
                f = __half22float2(*(__half2*)&v3.y); a2 += f.x; a3 += f.y;
            }
        }
        for (; i < m; i++) {
            int s0 = __shfl_sync(0xFFFFFFFFu, sidx, i);
            if (act) {
                uint2 v0 = *(const uint2*)(X + (size_t)s0 * CH + col);
                float2 f;
                f = __half22float2(*(__half2*)&v0.x); a0 += f.x; a1 += f.y;
                f = __half22float2(*(__half2*)&v0.y); a2 += f.x; a3 += f.y;
            }
        }
    }
    if (act) {
        float inv = g_inv_deg[node];
        __half2 p0 = __floats2half2_rn(a0 * inv, a1 * inv);
        __half2 p1 = __floats2half2_rn(a2 * inv, a3 * inv);
        uint2 pk;
        pk.x = *(unsigned*)&p0;
        pk.y = *(unsigned*)&p1;
        *(uint2*)(OUT + (size_t)node * CH + col) = pk;
    }
}

// ---------------- fp16 tensor-core dual-input GEMM ----------------
__device__ __forceinline__ void mma_f16(float* c, const unsigned* a, const unsigned* b) {
    asm volatile(
        "mma.sync.aligned.m16n8k16.row.col.f32.f16.f16.f32 "
        "{%0,%1,%2,%3}, {%4,%5,%6,%7}, {%8,%9}, {%0,%1,%2,%3};\n"
        : "+f"(c[0]), "+f"(c[1]), "+f"(c[2]), "+f"(c[3])
        : "r"(a[0]), "r"(a[1]), "r"(a[2]), "r"(a[3]),
          "r"(b[0]), "r"(b[1]));
}

template <int N, typename CT>
__global__ void __launch_bounds__(256)
gemm_h_kernel(const __half* __restrict__ A1, const float* __restrict__ W1, int K1,
              const __half* __restrict__ A2, const float* __restrict__ W2, int K2,
              const float* __restrict__ bias, int do_relu,
              CT* __restrict__ C, int Nrows) {
    constexpr int BM = 128, BK = 16, RS = 24;   // RS = smem row stride in halves
    constexpr int NT = N / 8;
    __shared__ __align__(16) __half As[BM * RS];
    __shared__ __align__(16) __half Wt[N * RS];

    const int tid  = threadIdx.x;
    const int warp = tid >> 5;
    const int lane = tid & 31;
    const int g  = lane >> 2;
    const int cq = lane & 3;
    const int rowBase = blockIdx.x * BM;

    float acc[NT][4];
#pragma unroll
    for (int nt = 0; nt < NT; nt++)
#pragma unroll
        for (int i = 0; i < 4; i++) acc[nt][i] = 0.0f;

    for (int part = 0; part < 2; part++) {
        const __half* A = (part == 0) ? A1 : A2;
        const float*  W = (part == 0) ? W1 : W2;
        const int K = (part == 0) ? K1 : K2;
        if (K == 0) continue;
        for (int k0 = 0; k0 < K; k0 += BK) {
            __syncthreads();
            // stage A: 128x16 halves; one uint4 (8 halves) per thread
            {
                int row = tid >> 1;
                int hc  = (tid & 1) * 8;
                int grow = rowBase + row;
                uint4 v = make_uint4(0, 0, 0, 0);
                if (grow < Nrows)
                    v = *(const uint4*)(A + (size_t)grow * K + k0 + hc);
                *(uint4*)(As + row * RS + hc) = v;
            }
            // stage W transposed: Wt[j][kk] = half(W[k0+kk][j])
            for (int idx = tid; idx < BK * N; idx += 256) {
                int kk = idx / N;
                int j  = idx - kk * N;
                Wt[j * RS + kk] = __float2half_rn(W[(size_t)(k0 + kk) * N + j]);
            }
            __syncthreads();
            unsigned a[4];
            const int r0 = (warp * 16 + g) * RS + 2 * cq;
            a[0] = *(const unsigned*)(As + r0);
            a[1] = *(const unsigned*)(As + r0 + 8 * RS);
            a[2] = *(const unsigned*)(As + r0 + 8);
            a[3] = *(const unsigned*)(As + r0 + 8 * RS + 8);
#pragma unroll
            for (int nt = 0; nt < NT; nt++) {
                unsigned b[2];
                const int wr = (nt * 8 + g) * RS + 2 * cq;
                b[0] = *(const unsigned*)(Wt + wr);
                b[1] = *(const unsigned*)(Wt + wr + 8);
                mma_f16(acc[nt], a, b);
            }
        }
    }
    const int row0 = rowBase + warp * 16 + g;
#pragma unroll
    for (int nt = 0; nt < NT; nt++) {
        int col = nt * 8 + 2 * cq;
        float v0 = acc[nt][0], v1 = acc[nt][1], v2 = acc[nt][2], v3 = acc[nt][3];
        if (bias) {
            float bc0 = bias[col], bc1 = bias[col + 1];
            v0 += bc0; v1 += bc1; v2 += bc0; v3 += bc1;
        }
        if (do_relu) {
            v0 = fmaxf(v0, 0.0f); v1 = fmaxf(v1, 0.0f);
            v2 = fmaxf(v2, 0.0f); v3 = fmaxf(v3, 0.0f);
        }
        if (row0 < Nrows) {
            CT* p = C + (size_t)row0 * N + col;
            if (sizeof(CT) == 2) {
                __half2 h = __floats2half2_rn(v0, v1);
                *(unsigned*)p = *(unsigned*)&h;
            } else {
                ((float*)p)[0] = v0; ((float*)p)[1] = v1;
            }
        }
        if (row0 + 8 < Nrows) {
            CT* p = C + (size_t)(row0 + 8) * N + col;
            if (sizeof(CT) == 2) {
                __half2 h = __floats2half2_rn(v2, v3);
                *(unsigned*)p = *(unsigned*)&h;
            } else {
                ((float*)p)[0] = v2; ((float*)p)[1] = v3;
            }
        }
    }
}

// ---------------- layer-3 weight concat: wcat[k, j] = j<40 ? w3_l : w3_r ----
__global__ void build_wcat_kernel(const float* __restrict__ w3l,
                                  const float* __restrict__ w3r) {
    int idx = blockIdx.x * blockDim.x + threadIdx.x;
    if (idx >= 128 * 80) return;
    int k = idx / 80, j = idx - k * 80;
    g_wcat[idx] = (j < 40) ? w3l[k * 40 + j] : w3r[k * 40 + (j - 40)];
}

// ---------------- fused: mean-agg of t[:, :40] + root + bias + log_softmax ----
__global__ void final_kernel(const float* __restrict__ b3,
                             float* __restrict__ out) {
    int node = (blockIdx.x * blockDim.x + threadIdx.x) >> 5;
    int lane = threadIdx.x & 31;
    if (node >= N_NODES) return;
    int beg = g_off[node], end = g_off[node + 1];
    float a0 = 0.f, a1 = 0.f;
    for (int c = beg; c < end; c += 32) {
        int m = end - c; if (m > 32) m = 32;
        int sidx = (lane < m) ? __ldg(g_src_sorted + c + lane) : 0;
        int i = 0;
        for (; i + 4 <= m; i += 4) {
            int s0 = __shfl_sync(0xFFFFFFFFu, sidx, i);
            int s1 = __shfl_sync(0xFFFFFFFFu, sidx, i + 1);
            int s2 = __shfl_sync(0xFFFFFFFFu, sidx, i + 2);
            int s3 = __shfl_sync(0xFFFFFFFFu, sidx, i + 3);
            const float* r0 = g_t + (size_t)s0 * 80;
            const float* r1 = g_t + (size_t)s1 * 80;
            const float* r2 = g_t + (size_t)s2 * 80;
            const float* r3 = g_t + (size_t)s3 * 80;
            a0 += __ldg(r0 + lane) + __ldg(r1 + lane) + __ldg(r2 + lane) + __ldg(r3 + lane);
            if (lane < 8)
                a1 += __ldg(r0 + 32 + lane) + __ldg(r1 + 32 + lane)
                    + __ldg(r2 + 32 + lane) + __ldg(r3 + 32 + lane);
        }
        for (; i < m; i++) {
            int s0 = __shfl_sync(0xFFFFFFFFu, sidx, i);
            const float* r0 = g_t + (size_t)s0 * 80;
            a0 += __ldg(r0 + lane);
            if (lane < 8) a1 += __ldg(r0 + 32 + lane);
        }
    }
    float inv = g_inv_deg[node];
    const float* tr = g_t + (size_t)node * 80 + 40;   // root transform
    float v0 = a0 * inv + tr[lane] + b3[lane];
    float v1 = -INFINITY;
    if (lane < 8) v1 = a1 * inv + tr[32 + lane] + b3[32 + lane];
    float m = fmaxf(v0, v1);
#pragma unroll
    for (int s = 16; s; s >>= 1) m = fmaxf(m, __shfl_xor_sync(0xFFFFFFFFu, m, s));
    float e = __expf(v0 - m) + ((lane < 8) ? __expf(v1 - m) : 0.0f);
#pragma unroll
    for (int s = 16; s; s >>= 1) e += __shfl_xor_sync(0xFFFFFFFFu, e, s);
    float lse = m + logf(e);
    float* orow = out + (size_t)node * 40;
    orow[lane] = v0 - lse;
    if (lane < 8) orow[lane + 32] = v1 - lse;
}

// ---------------- launch ----------------
extern "C" void kernel_launch(void* const* d_in, const int* in_sizes, int n_in,
                              void* d_out, int out_size) {
    const float* x    = (const float*)d_in[0];
    const int*   ei   = (const int*)d_in[1];   // [2, E] int32: row0=src, row1=dst
    const float* w1_l = (const float*)d_in[2];
    const float* w1_r = (const float*)d_in[3];
    const float* b1   = (const float*)d_in[4];
    const float* w2_l = (const float*)d_in[5];
    const float* w2_r = (const float*)d_in[6];
    const float* b2   = (const float*)d_in[7];
    const float* w3_l = (const float*)d_in[8];
    const float* w3_r = (const float*)d_in[9];
    const float* b3   = (const float*)d_in[10];
    float* out = (float*)d_out;

    const int* src = ei;
    const int* dst = ei + N_EDGES;

    __half *xh, *agg, *h1, *h2;
    float *t, *wcat;
    cudaGetSymbolAddress((void**)&xh,   g_xh);
    cudaGetSymbolAddress((void**)&agg,  g_agg);
    cudaGetSymbolAddress((void**)&h1,   g_h1);
    cudaGetSymbolAddress((void**)&h2,   g_h2);
    cudaGetSymbolAddress((void**)&t,    g_t);
    cudaGetSymbolAddress((void**)&wcat, g_wcat);

    const int TB = 256;
    const int convThreads = (N_NODES * 64) / 4;                 // 1.6M
    const int histBlocks = (convThreads + TB - 1) / TB;         // covers edges too
    const int warpBlocks = (N_NODES * 32 + TB - 1) / TB;        // one warp per node
    const int gemmBlocks = (N_NODES + 127) / 128;

    // CSR build + x->fp16 (g_count re-zeroed inside scanC for graph replay)
    hist_conv_kernel<<<histBlocks, TB>>>(dst, x);
    scanA_kernel<<<SCAN_NB, 1024>>>();
    scanC_kernel<<<SCAN_NB, 1024>>>();
    scatter_kernel<<<(N_EDGES + TB - 1) / TB, TB>>>(src, dst);
    sort_kernel<<<warpBlocks, TB>>>();
    build_wcat_kernel<<<(128 * 80 + TB - 1) / TB, TB>>>(w3_l, w3_r);

    // Layer 1: aggregate xh (64), h1 = relu(agg@w1_l + xh@w1_r + b1)  [fp16 out]
    aggregate_h_kernel<64><<<warpBlocks, TB>>>(xh, agg);
    gemm_h_kernel<128, __half><<<gemmBlocks, TB>>>(agg, w1_l, 64, xh, w1_r, 64,
                                                   b1, 1, h1, N_NODES);

    // Layer 2: aggregate h1 (128), h2 = relu(agg@w2_l + h1@w2_r + b2)  [fp16 out]
    aggregate_h_kernel<128><<<warpBlocks, TB>>>(h1, agg);
    gemm_h_kernel<128, __half><<<gemmBlocks, TB>>>(agg, w2_l, 128, h1, w2_r, 128,
                                                   b2, 1, h2, N_NODES);

    // Layer 3: transform FIRST (linearity), t = h2 @ wcat  [fp32 out, 80 wide]
    gemm_h_kernel<80, float><<<gemmBlocks, TB>>>(h2, wcat, 128,
                                                 (const __half*)0, (const float*)0, 0,
                                                 (const float*)0, 0, t, N_NODES);
    // fused: mean-agg of t[:, :40] + root t[:, 40:] + b3 + log_softmax
    final_kernel<<<warpBlocks, TB>>>(b3, out);
}

// round 7
// speedup vs baseline: 3.5823x; 1.3798x over previous
#include <cuda_runtime.h>
#include <cuda_fp16.h>
#include <math.h>

#define N_NODES 100000
#define N_EDGES 1000000
#define SCAN_NB 98   // ceil(100000/1024)

// ---------------- scratch (static device globals; no allocation) ----------------
__device__ int    g_count[N_NODES];
__device__ int    g_off[N_NODES + 1];
__device__ int    g_cur[N_NODES];
__device__ int    g_bsum[128];
__device__ int    g_src_sorted[N_EDGES];
__device__ float  g_inv_deg[N_NODES];
__device__ __half g_xh [(size_t)N_NODES * 64];
__device__ __half g_agg[(size_t)N_NODES * 128];
__device__ __half g_h1 [(size_t)N_NODES * 128];
__device__ __half g_h2 [(size_t)N_NODES * 128];
__device__ float  g_t  [(size_t)N_NODES * 80];
// pre-converted fp16 weights, k-contiguous per output column j: W[j][k]
__device__ __half g_wh1[128 * 128];   // layer1: [j=0..127][k: 0..63=w1_l, 64..127=w1_r]
__device__ __half g_wh2[128 * 256];   // layer2: [j][k: 0..127=w2_l, 128..255=w2_r]
__device__ __half g_wh3[80 * 128];    // layer3: [j<40 -> w3_l col j][j>=40 -> w3_r col j-40]

// ---------------- hist + x->fp16 convert (fused) ----------------
__global__ void hist_conv_kernel(const int* __restrict__ dst,
                                 const float* __restrict__ x) {
    int i = blockIdx.x * blockDim.x + threadIdx.x;
    if (i < N_EDGES) atomicAdd(&g_count[dst[i]], 1);
    int base = i * 4;
    if (base < N_NODES * 64) {
        float4 v = *(const float4*)(x + base);
        __half2 p0 = __floats2half2_rn(v.x, v.y);
        __half2 p1 = __floats2half2_rn(v.z, v.w);
        uint2 pk;
        pk.x = *(unsigned*)&p0;
        pk.y = *(unsigned*)&p1;
        *(uint2*)(g_xh + base) = pk;
    }
}

// ---------------- 3-phase coalesced scan ----------------
__global__ void scanA_kernel() {
    __shared__ int s[1024];
    const int t = threadIdx.x;
    const int i = blockIdx.x * 1024 + t;
    int c = (i < N_NODES) ? g_count[i] : 0;
    s[t] = c;
    __syncthreads();
    for (int d = 1; d < 1024; d <<= 1) {
        int v = (t >= d) ? s[t - d] : 0;
        __syncthreads();
        s[t] += v;
        __syncthreads();
    }
    if (i < N_NODES) g_off[i] = s[t] - c;
    if (t == 1023) g_bsum[blockIdx.x] = s[1023];
}

__global__ void scanC_kernel() {
    __shared__ int bs[SCAN_NB];
    const int t = threadIdx.x;
    if (t < SCAN_NB) bs[t] = g_bsum[t];
    __syncthreads();
    if (t == 0) {
        int run = 0;
        for (int b = 0; b < SCAN_NB; b++) { int c = bs[b]; bs[b] = run; run += c; }
        if (blockIdx.x == 0) g_off[N_NODES] = run;
    }
    __syncthreads();
    int i = blockIdx.x * 1024 + t;
    if (i < N_NODES) {
        int off = g_off[i] + bs[blockIdx.x];
        int c = g_count[i];
        g_off[i] = off;
        g_cur[i] = off;
        g_inv_deg[i] = 1.0f / (float)(c > 1 ? c : 1);
        g_count[i] = 0;                         // re-zero for next graph replay
    }
}

__global__ void scatter_kernel(const int* __restrict__ src,
                               const int* __restrict__ dst) {
    int e = blockIdx.x * blockDim.x + threadIdx.x;
    if (e < N_EDGES) {
        int d = dst[e];
        int p = atomicAdd(&g_cur[d], 1);
        g_src_sorted[p] = src[e];
    }
}

// ---------------- deterministic neighbor order: warp bitonic sort ----------------
__global__ void sort_kernel() {
    int node = (blockIdx.x * blockDim.x + threadIdx.x) >> 5;
    int lane = threadIdx.x & 31;
    if (node >= N_NODES) return;
    int beg = g_off[node], end = g_off[node + 1];
    int deg = end - beg;
    if (deg <= 1) return;
    if (deg <= 32) {
        int v = (lane < deg) ? g_src_sorted[beg + lane] : 0x7FFFFFFF;
#pragma unroll
        for (int k = 2; k <= 32; k <<= 1) {
#pragma unroll
            for (int j = k >> 1; j; j >>= 1) {
                int o = __shfl_xor_sync(0xFFFFFFFFu, v, j);
                bool up    = ((lane & k) == 0);
                bool lower = ((lane & j) == 0);
                v = (up == lower) ? min(v, o) : max(v, o);
            }
        }
        if (lane < deg) g_src_sorted[beg + lane] = v;
    } else if (lane == 0) {
        for (int i = beg + 1; i < end; i++) {
            int key = g_src_sorted[i];
            int j = i - 1;
            while (j >= beg && g_src_sorted[j] > key) {
                g_src_sorted[j + 1] = g_src_sorted[j];
                j--;
            }
            g_src_sorted[j + 1] = key;
        }
    }
}

// ---------------- weight prep: fp32 -> fp16, transposed to [j][k] k-contig ------
__global__ void prep_w_kernel(const float* __restrict__ w1l, const float* __restrict__ w1r,
                              const float* __restrict__ w2l, const float* __restrict__ w2r,
                              const float* __restrict__ w3l, const float* __restrict__ w3r) {
    int i = blockIdx.x * blockDim.x + threadIdx.x;
    if (i < 128 * 128) {
        int j = i >> 7, k = i & 127;
        float v = (k < 64) ? w1l[k * 128 + j] : w1r[(k - 64) * 128 + j];
        g_wh1[j * 128 + k] = __float2half_rn(v);
    }
    i -= 128 * 128;
    if (i >= 0 && i < 128 * 256) {
        int j = i >> 8, k = i & 255;
        float v = (k < 128) ? w2l[k * 128 + j] : w2r[(k - 128) * 128 + j];
        g_wh2[j * 256 + k] = __float2half_rn(v);
    }
    i -= 128 * 256;
    if (i >= 0 && i < 80 * 128) {
        int j = i >> 7, k = i & 127;
        float v = (j < 40) ? w3l[k * 40 + j] : w3r[k * 40 + (j - 40)];
        g_wh3[j * 128 + k] = __float2half_rn(v);
    }
}

// ---------------- mean-aggregation (fp16 rows): one warp per dst node ----------
template <int CH>
__global__ void aggregate_h_kernel(const __half* __restrict__ X,
                                   __half* __restrict__ OUT) {
    int node = (blockIdx.x * blockDim.x + threadIdx.x) >> 5;
    int lane = threadIdx.x & 31;
    if (node >= N_NODES) return;
    const bool act = (4 * lane < CH);
    const int col = 4 * lane;
    int beg = g_off[node], end = g_off[node + 1];
    float a0 = 0.f, a1 = 0.f, a2 = 0.f, a3 = 0.f;
    for (int c = beg; c < end; c += 32) {
        int m = end - c; if (m > 32) m = 32;
        int sidx = (lane < m) ? __ldg(g_src_sorted + c + lane) : 0;
        int i = 0;
        for (; i + 4 <= m; i += 4) {
            int s0 = __shfl_sync(0xFFFFFFFFu, sidx, i);
            int s1 = __shfl_sync(0xFFFFFFFFu, sidx, i + 1);
            int s2 = __shfl_sync(0xFFFFFFFFu, sidx, i + 2);
            int s3 = __shfl_sync(0xFFFFFFFFu, sidx, i + 3);
            if (act) {
                uint2 v0 = *(const uint2*)(X + (size_t)s0 * CH + col);
                uint2 v1 = *(const uint2*)(X + (size_t)s1 * CH + col);
                uint2 v2 = *(const uint2*)(X + (size_t)s2 * CH + col);
                uint2 v3 = *(const uint2*)(X + (size_t)s3 * CH + col);
                float2 f;
                f = __half22float2(*(__half2*)&v0.x); a0 += f.x; a1 += f.y;
                f = __half22float2(*(__half2*)&v0.y); a2 += f.x; a3 += f.y;
                f = __half22float2(*(__half2*)&v1.x); a0 += f.x; a1 += f.y;
                f = __half22float2(*(__half2*)&v1.y); a2 += f.x; a3 += f.y;
                f = __half22float2(*(__half2*)&v2.x); a0 += f.x; a1 += f.y;
                f = __half22float2(*(__half2*)&v2.y); a2 += f.x; a3 += f.y;
                f = __half22float2(*(__half2*)&v3.x); a0 += f.x; a1 += f.y;
                f = __half22float2(*(__half2*)&v3.y); a2 += f.x; a3 += f.y;
            }
        }
        for (; i < m; i++) {
            int s0 = __shfl_sync(0xFFFFFFFFu, sidx, i);
            if (act) {
                uint2 v0 = *(const uint2*)(X + (size_t)s0 * CH + col);
                float2 f;
                f = __half22float2(*(__half2*)&v0.x); a0 += f.x; a1 += f.y;
                f = __half22float2(*(__half2*)&v0.y); a2 += f.x; a3 += f.y;
            }
        }
    }
    if (act) {
        float inv = g_inv_deg[node];
        __half2 p0 = __floats2half2_rn(a0 * inv, a1 * inv);
        __half2 p1 = __floats2half2_rn(a2 * inv, a3 * inv);
        uint2 pk;
        pk.x = *(unsigned*)&p0;
        pk.y = *(unsigned*)&p1;
        *(uint2*)(OUT + (size_t)node * CH + col) = pk;
    }
}

// ---------------- cp.async helpers ----------------
__device__ __forceinline__ void cp16(void* smem, const void* gmem, bool pred) {
    unsigned saddr = (unsigned)__cvta_generic_to_shared(smem);
    int sz = pred ? 16 : 0;
    asm volatile("cp.async.cg.shared.global [%0], [%1], 16, %2;\n"
                 :: "r"(saddr), "l"(gmem), "r"(sz));
}
__device__ __forceinline__ void cp_commit() {
    asm volatile("cp.async.commit_group;\n");
}
template <int NN>
__device__ __forceinline__ void cp_wait() {
    asm volatile("cp.async.wait_group %0;\n" :: "n"(NN));
}

__device__ __forceinline__ void mma_f16(float* c, const unsigned* a, const unsigned* b) {
    asm volatile(
        "mma.sync.aligned.m16n8k16.row.col.f32.f16.f16.f32 "
        "{%0,%1,%2,%3}, {%4,%5,%6,%7}, {%8,%9}, {%0,%1,%2,%3};\n"
        : "+f"(c[0]), "+f"(c[1]), "+f"(c[2]), "+f"(c[3])
        : "r"(a[0]), "r"(a[1]), "r"(a[2]), "r"(a[3]),
          "r"(b[0]), "r"(b[1]));
}

// ---------------- cp.async double-buffered fp16 GEMM ----------------
// C = [A1|A2] @ Wh^T + bias (optional relu). Wh is [N][K1+K2] fp16 k-contig.
// BM=128 rows/CTA, BK=32, 8 warps x 16 rows, each warp computes all N cols.
// SMEM row stride RS=40 halves: MMA-read banks {20g+cq mod 32} conflict-free.
template <int N, typename CT>
__global__ void __launch_bounds__(256)
gemm_cp_kernel(const __half* __restrict__ A1, int K1,
               const __half* __restrict__ A2, int K2,
               const __half* __restrict__ Wh,
               const float* __restrict__ bias, int do_relu,
               CT* __restrict__ C, int Nrows) {
    constexpr int BM = 128, BK = 32, RS = 40;
    constexpr int NT = N / 8;
    __shared__ __align__(16) __half As[2][BM * RS];
    __shared__ __align__(16) __half Ws[2][N * RS];

    const int tid  = threadIdx.x;
    const int warp = tid >> 5;
    const int lane = tid & 31;
    const int g  = lane >> 2;
    const int cq = lane & 3;
    const int rowBase = blockIdx.x * BM;
    const int Ktot = K1 + K2;
    const int T = Ktot / BK;

    float acc[NT][4];
#pragma unroll
    for (int nt = 0; nt < NT; nt++)
#pragma unroll
        for (int i = 0; i < 4; i++) acc[nt][i] = 0.0f;

    auto issue = [&](int tt, int buf) {
        int kbase = tt * BK;
        const __half* A;
        int kloc, Kst;
        if (kbase < K1) { A = A1; kloc = kbase;      Kst = K1; }
        else            { A = A2; kloc = kbase - K1; Kst = K2; }
        // A tile: 128 rows x 32 halves = 512 x 16B chunks, 2 per thread
#pragma unroll
        for (int i = 0; i < 2; i++) {
            int c = tid + 256 * i;
            int row = c >> 2, part = c & 3;
            int grow = rowBase + row;
            const void* src = A + (size_t)grow * Kst + kloc + part * 8;
            cp16(&As[buf][row * RS + part * 8], src, grow < Nrows);
        }
        // W tile: N rows x 32 halves
        for (int c = tid; c < N * 4; c += 256) {
            int j = c >> 2, part = c & 3;
            const void* src = Wh + (size_t)j * Ktot + kbase + part * 8;
            cp16(&Ws[buf][j * RS + part * 8], src, true);
        }
    };

    issue(0, 0);
    cp_commit();
    for (int t = 0; t < T; t++) {
        const int buf = t & 1;
        if (t + 1 < T) { issue(t + 1, (t + 1) & 1); cp_commit(); cp_wait<1>(); }
        else           { cp_wait<0>(); }
        __syncthreads();
#pragma unroll
        for (int ks = 0; ks < BK; ks += 16) {
            unsigned a[4];
            const __half* ab = &As[buf][(warp * 16 + g) * RS + ks + 2 * cq];
            a[0] = *(const unsigned*)ab;
            a[1] = *(const unsigned*)(ab + 8 * RS);
            a[2] = *(const unsigned*)(ab + 8);
            a[3] = *(const unsigned*)(ab + 8 * RS + 8);
#pragma unroll
            for (int nt = 0; nt < NT; nt++) {
                unsigned b[2];
                const __half* bb = &Ws[buf][(nt * 8 + g) * RS + ks + 2 * cq];
                b[0] = *(const unsigned*)bb;
                b[1] = *(const unsigned*)(bb + 8);
                mma_f16(acc[nt], a, b);
            }
        }
        __syncthreads();
    }

    const int row0 = rowBase + warp * 16 + g;
#pragma unroll
    for (int nt = 0; nt < NT; nt++) {
        int col = nt * 8 + 2 * cq;
        float v0 = acc[nt][0], v1 = acc[nt][1], v2 = acc[nt][2], v3 = acc[nt][3];
        if (bias) {
            float bc0 = bias[col], bc1 = bias[col + 1];
            v0 += bc0; v1 += bc1; v2 += bc0; v3 += bc1;
        }
        if (do_relu) {
            v0 = fmaxf(v0, 0.0f); v1 = fmaxf(v1, 0.0f);
            v2 = fmaxf(v2, 0.0f); v3 = fmaxf(v3, 0.0f);
        }
        if (row0 < Nrows) {
            CT* p = C + (size_t)row0 * N + col;
            if (sizeof(CT) == 2) {
                __half2 h = __floats2half2_rn(v0, v1);
                *(unsigned*)p = *(unsigned*)&h;
            } else {
                ((float*)p)[0] = v0; ((float*)p)[1] = v1;
            }
        }
        if (row0 + 8 < Nrows) {
            CT* p = C + (size_t)(row0 + 8) * N + col;
            if (sizeof(CT) == 2) {
                __half2 h = __floats2half2_rn(v2, v3);
                *(unsigned*)p = *(unsigned*)&h;
            } else {
                ((float*)p)[0] = v2; ((float*)p)[1] = v3;
            }
        }
    }
}

// ---------------- fused: mean-agg of t[:, :40] + root + bias + log_softmax ----
__global__ void final_kernel(const float* __restrict__ b3,
                             float* __restrict__ out) {
    int node = (blockIdx.x * blockDim.x + threadIdx.x) >> 5;
    int lane = threadIdx.x & 31;
    if (node >= N_NODES) return;
    int beg = g_off[node], end = g_off[node + 1];
    float a0 = 0.f, a1 = 0.f;
    for (int c = beg; c < end; c += 32) {
        int m = end - c; if (m > 32) m = 32;
        int sidx = (lane < m) ? __ldg(g_src_sorted + c + lane) : 0;
        int i = 0;
        for (; i + 4 <= m; i += 4) {
            int s0 = __shfl_sync(0xFFFFFFFFu, sidx, i);
            int s1 = __shfl_sync(0xFFFFFFFFu, sidx, i + 1);
            int s2 = __shfl_sync(0xFFFFFFFFu, sidx, i + 2);
            int s3 = __shfl_sync(0xFFFFFFFFu, sidx, i + 3);
            const float* r0 = g_t + (size_t)s0 * 80;
            const float* r1 = g_t + (size_t)s1 * 80;
            const float* r2 = g_t + (size_t)s2 * 80;
            const float* r3 = g_t + (size_t)s3 * 80;
            a0 += __ldg(r0 + lane) + __ldg(r1 + lane) + __ldg(r2 + lane) + __ldg(r3 + lane);
            if (lane < 8)
                a1 += __ldg(r0 + 32 + lane) + __ldg(r1 + 32 + lane)
                    + __ldg(r2 + 32 + lane) + __ldg(r3 + 32 + lane);
        }
        for (; i < m; i++) {
            int s0 = __shfl_sync(0xFFFFFFFFu, sidx, i);
            const float* r0 = g_t + (size_t)s0 * 80;
            a0 += __ldg(r0 + lane);
            if (lane < 8) a1 += __ldg(r0 + 32 + lane);
        }
    }
    float inv = g_inv_deg[node];
    const float* tr = g_t + (size_t)node * 80 + 40;
    float v0 = a0 * inv + tr[lane] + b3[lane];
    float v1 = -INFINITY;
    if (lane < 8) v1 = a1 * inv + tr[32 + lane] + b3[32 + lane];
    float m = fmaxf(v0, v1);
#pragma unroll
    for (int s = 16; s; s >>= 1) m = fmaxf(m, __shfl_xor_sync(0xFFFFFFFFu, m, s));
    float e = __expf(v0 - m) + ((lane < 8) ? __expf(v1 - m) : 0.0f);
#pragma unroll
    for (int s = 16; s; s >>= 1) e += __shfl_xor_sync(0xFFFFFFFFu, e, s);
    float lse = m + logf(e);
    float* orow = out + (size_t)node * 40;
    orow[lane] = v0 - lse;
    if (lane < 8) orow[lane + 32] = v1 - lse;
}

// ---------------- launch ----------------
extern "C" void kernel_launch(void* const* d_in, const int* in_sizes, int n_in,
                              void* d_out, int out_size) {
    const float* x    = (const float*)d_in[0];
    const int*   ei   = (const int*)d_in[1];   // [2, E] int32: row0=src, row1=dst
    const float* w1_l = (const float*)d_in[2];
    const float* w1_r = (const float*)d_in[3];
    const float* b1   = (const float*)d_in[4];
    const float* w2_l = (const float*)d_in[5];
    const float* w2_r = (const float*)d_in[6];
    const float* b2   = (const float*)d_in[7];
    const float* w3_l = (const float*)d_in[8];
    const float* w3_r = (const float*)d_in[9];
    const float* b3   = (const float*)d_in[10];
    float* out = (float*)d_out;

    const int* src = ei;
    const int* dst = ei + N_EDGES;

    __half *xh, *agg, *h1, *h2, *wh1, *wh2, *wh3;
    float *t;
    cudaGetSymbolAddress((void**)&xh,  g_xh);
    cudaGetSymbolAddress((void**)&agg, g_agg);
    cudaGetSymbolAddress((void**)&h1,  g_h1);
    cudaGetSymbolAddress((void**)&h2,  g_h2);
    cudaGetSymbolAddress((void**)&t,   g_t);
    cudaGetSymbolAddress((void**)&wh1, g_wh1);
    cudaGetSymbolAddress((void**)&wh2, g_wh2);
    cudaGetSymbolAddress((void**)&wh3, g_wh3);

    const int TB = 256;
    const int convThreads = (N_NODES * 64) / 4;                 // 1.6M
    const int histBlocks = (convThreads + TB - 1) / TB;
    const int warpBlocks = (N_NODES * 32 + TB - 1) / TB;        // one warp per node
    const int gemmBlocks = (N_NODES + 127) / 128;
    const int prepTotal  = 128 * 128 + 128 * 256 + 80 * 128;

    // CSR build + x->fp16 (g_count re-zeroed inside scanC for graph replay)
    hist_conv_kernel<<<histBlocks, TB>>>(dst, x);
    scanA_kernel<<<SCAN_NB, 1024>>>();
    scanC_kernel<<<SCAN_NB, 1024>>>();
    scatter_kernel<<<(N_EDGES + TB - 1) / TB, TB>>>(src, dst);
    sort_kernel<<<warpBlocks, TB>>>();
    prep_w_kernel<<<(prepTotal + TB - 1) / TB, TB>>>(w1_l, w1_r, w2_l, w2_r, w3_l, w3_r);

    // Layer 1: aggregate xh (64), h1 = relu([agg|xh] @ wh1^T + b1)  [fp16 out]
    aggregate_h_kernel<64><<<warpBlocks, TB>>>(xh, agg);
    gemm_cp_kernel<128, __half><<<gemmBlocks, TB>>>(agg, 64, xh, 64, wh1,
                                                    b1, 1, h1, N_NODES);

    // Layer 2: aggregate h1 (128), h2 = relu([agg|h1] @ wh2^T + b2)  [fp16 out]
    aggregate_h_kernel<128><<<warpBlocks, TB>>>(h1, agg);
    gemm_cp_kernel<128, __half><<<gemmBlocks, TB>>>(agg, 128, h1, 128, wh2,
                                                    b2, 1, h2, N_NODES);

    // Layer 3: transform FIRST (linearity), t = h2 @ wh3^T  [fp32 out, 80 wide]
    gemm_cp_kernel<80, float><<<gemmBlocks, TB>>>(h2, 128, (const __half*)0, 0, wh3,
                                                  (const float*)0, 0, t, N_NODES);
    // fused: mean-agg of t[:, :40] + root t[:, 40:] + b3 + log_softmax
    final_kernel<<<warpBlocks, TB>>>(b3, out);
}

// round 8
// speedup vs baseline: 3.8496x; 1.0746x over previous
#include <cuda_runtime.h>
#include <cuda_fp16.h>
#include <math.h>

#define N_NODES 100000
#define N_EDGES 1000000
#define SCAN_NB 98   // ceil(100000/1024)

// ---------------- scratch (static device globals; no allocation) ----------------
__device__ int    g_count[N_NODES];
__device__ int    g_off[N_NODES + 1];
__device__ int    g_cur[N_NODES];
__device__ int    g_bsum[128];
__device__ int    g_src_sorted[N_EDGES];
__device__ float  g_inv_deg[N_NODES];
__device__ __half g_xh [(size_t)N_NODES * 64];
__device__ __half g_agg[(size_t)N_NODES * 128];
__device__ __half g_h1 [(size_t)N_NODES * 128];
__device__ __half g_h2 [(size_t)N_NODES * 128];
__device__ float  g_t  [(size_t)N_NODES * 80];
// pre-converted fp16 weights, k-contiguous per output column j: W[j][k]
__device__ __half g_wh1[128 * 128];
__device__ __half g_wh2[128 * 256];
__device__ __half g_wh3[80 * 128];

#define PREP_TOTAL (128 * 128 + 128 * 256 + 80 * 128)

// ---------------- hist + x->fp16 convert + weight prep (fused) ----------------
__global__ void hist_conv_kernel(const int* __restrict__ dst,
                                 const float* __restrict__ x,
                                 const float* __restrict__ w1l, const float* __restrict__ w1r,
                                 const float* __restrict__ w2l, const float* __restrict__ w2r,
                                 const float* __restrict__ w3l, const float* __restrict__ w3r) {
    int i = blockIdx.x * blockDim.x + threadIdx.x;
    if (i < N_EDGES) atomicAdd(&g_count[dst[i]], 1);
    int base = i * 4;
    if (base < N_NODES * 64) {
        float4 v = *(const float4*)(x + base);
        __half2 p0 = __floats2half2_rn(v.x, v.y);
        __half2 p1 = __floats2half2_rn(v.z, v.w);
        uint2 pk;
        pk.x = *(unsigned*)&p0;
        pk.y = *(unsigned*)&p1;
        *(uint2*)(g_xh + base) = pk;
    }
    // weight prep (first 59k threads)
    int p = i;
    if (p < 128 * 128) {
        int j = p >> 7, k = p & 127;
        float v = (k < 64) ? w1l[k * 128 + j] : w1r[(k - 64) * 128 + j];
        g_wh1[j * 128 + k] = __float2half_rn(v);
        return;
    }
    p -= 128 * 128;
    if (p >= 0 && p < 128 * 256) {
        int j = p >> 8, k = p & 255;
        float v = (k < 128) ? w2l[k * 128 + j] : w2r[(k - 128) * 128 + j];
        g_wh2[j * 256 + k] = __float2half_rn(v);
        return;
    }
    p -= 128 * 256;
    if (p >= 0 && p < 80 * 128) {
        int j = p >> 7, k = p & 127;
        float v = (j < 40) ? w3l[k * 40 + j] : w3r[k * 40 + (j - 40)];
        g_wh3[j * 128 + k] = __float2half_rn(v);
    }
}

// ---------------- 3-phase coalesced scan ----------------
__global__ void scanA_kernel() {
    __shared__ int s[1024];
    const int t = threadIdx.x;
    const int i = blockIdx.x * 1024 + t;
    int c = (i < N_NODES) ? g_count[i] : 0;
    s[t] = c;
    __syncthreads();
    for (int d = 1; d < 1024; d <<= 1) {
        int v = (t >= d) ? s[t - d] : 0;
        __syncthreads();
        s[t] += v;
        __syncthreads();
    }
    if (i < N_NODES) g_off[i] = s[t] - c;
    if (t == 1023) g_bsum[blockIdx.x] = s[1023];
}

__global__ void scanC_kernel() {
    __shared__ int bs[SCAN_NB];
    const int t = threadIdx.x;
    if (t < SCAN_NB) bs[t] = g_bsum[t];
    __syncthreads();
    if (t == 0) {
        int run = 0;
        for (int b = 0; b < SCAN_NB; b++) { int c = bs[b]; bs[b] = run; run += c; }
        if (blockIdx.x == 0) g_off[N_NODES] = run;
    }
    __syncthreads();
    int i = blockIdx.x * 1024 + t;
    if (i < N_NODES) {
        int off = g_off[i] + bs[blockIdx.x];
        int c = g_count[i];
        g_off[i] = off;
        g_cur[i] = off;
        g_inv_deg[i] = 1.0f / (float)(c > 1 ? c : 1);
        g_count[i] = 0;                         // re-zero for next graph replay
    }
}

__global__ void scatter_kernel(const int* __restrict__ src,
                               const int* __restrict__ dst) {
    int e = blockIdx.x * blockDim.x + threadIdx.x;
    if (e < N_EDGES) {
        int d = dst[e];
        int p = atomicAdd(&g_cur[d], 1);
        g_src_sorted[p] = src[e];
    }
}

// ---------------- deterministic neighbor order: warp bitonic sort ----------------
__global__ void sort_kernel() {
    int node = (blockIdx.x * blockDim.x + threadIdx.x) >> 5;
    int lane = threadIdx.x & 31;
    if (node >= N_NODES) return;
    int beg = g_off[node], end = g_off[node + 1];
    int deg = end - beg;
    if (deg <= 1) return;
    if (deg <= 32) {
        int v = (lane < deg) ? g_src_sorted[beg + lane] : 0x7FFFFFFF;
#pragma unroll
        for (int k = 2; k <= 32; k <<= 1) {
#pragma unroll
            for (int j = k >> 1; j; j >>= 1) {
                int o = __shfl_xor_sync(0xFFFFFFFFu, v, j);
                bool up    = ((lane & k) == 0);
                bool lower = ((lane & j) == 0);
                v = (up == lower) ? min(v, o) : max(v, o);
            }
        }
        if (lane < deg) g_src_sorted[beg + lane] = v;
    } else if (lane == 0) {
        for (int i = beg + 1; i < end; i++) {
            int key = g_src_sorted[i];
            int j = i - 1;
            while (j >= beg && g_src_sorted[j] > key) {
                g_src_sorted[j + 1] = g_src_sorted[j];
                j--;
            }
            g_src_sorted[j + 1] = key;
        }
    }
}

// ---------------- mean-agg, 64-wide: TWO nodes per warp (half-warp each) --------
__global__ void aggregate64_kernel(const __half* __restrict__ X,
                                   __half* __restrict__ OUT) {
    int gw   = (blockIdx.x * blockDim.x + threadIdx.x) >> 5;
    int lane = threadIdx.x & 31;
    int hw   = lane >> 4;            // which half-warp (node within pair)
    int sl   = lane & 15;
    int node = gw * 2 + hw;
    if (node >= N_NODES) return;     // N even: whole warp exits together
    const int col = 4 * sl;          // 0..60
    int beg = g_off[node], end = g_off[node + 1];
    int deg = end - beg;
    int mx  = max(deg, __shfl_xor_sync(0xFFFFFFFFu, deg, 16));  // common trip count
    float a0 = 0.f, a1 = 0.f, a2 = 0.f, a3 = 0.f;
    for (int c = 0; c < mx; c += 16) {
        int m = deg - c; if (m > 16) m = 16;          // may be <= 0 for this half
        int sidx = (sl < m) ? __ldg(g_src_sorted + beg + c + sl) : 0;
        int mm = mx - c; if (mm > 16) mm = 16;        // common inner bound
        for (int i = 0; i < mm; i += 4) {
            int s0 = __shfl_sync(0xFFFFFFFFu, sidx, i,     16);
            int s1 = __shfl_sync(0xFFFFFFFFu, sidx, i + 1, 16);
            int s2 = __shfl_sync(0xFFFFFFFFu, sidx, i + 2, 16);
            int s3 = __shfl_sync(0xFFFFFFFFu, sidx, i + 3, 16);
            float2 f;
            if (i < m) {
                uint2 v = *(const uint2*)(X + (size_t)s0 * 64 + col);
                f = __half22float2(*(__half2*)&v.x); a0 += f.x; a1 += f.y;
                f = __half22float2(*(__half2*)&v.y); a2 += f.x; a3 += f.y;
            }
            if (i + 1 < m) {
                uint2 v = *(const uint2*)(X + (size_t)s1 * 64 + col);
                f = __half22float2(*(__half2*)&v.x); a0 += f.x; a1 += f.y;
                f = __half22float2(*(__half2*)&v.y); a2 += f.x; a3 += f.y;
            }
            if (i + 2 < m) {
                uint2 v = *(const uint2*)(X + (size_t)s2 * 64 + col);
                f = __half22float2(*(__half2*)&v.x); a0 += f.x; a1 += f.y;
                f = __half22float2(*(__half2*)&v.y); a2 += f.x; a3 += f.y;
            }
            if (i + 3 < m) {
                uint2 v = *(const uint2*)(X + (size_t)s3 * 64 + col);
                f = __half22float2(*(__half2*)&v.x); a0 += f.x; a1 += f.y;
                f = __half22float2(*(__half2*)&v.y); a2 += f.x; a3 += f.y;
            }
        }
    }
    float inv = g_inv_deg[node];
    __half2 p0 = __floats2half2_rn(a0 * inv, a1 * inv);
    __half2 p1 = __floats2half2_rn(a2 * inv, a3 * inv);
    uint2 pk;
    pk.x = *(unsigned*)&p0;
    pk.y = *(unsigned*)&p1;
    *(uint2*)(OUT + (size_t)node * 64 + col) = pk;
}

// ---------------- mean-agg, 128-wide: one warp per node --------------------------
__global__ void aggregate128_kernel(const __half* __restrict__ X,
                                    __half* __restrict__ OUT) {
    int node = (blockIdx.x * blockDim.x + threadIdx.x) >> 5;
    int lane = threadIdx.x & 31;
    if (node >= N_NODES) return;
    const int col = 4 * lane;
    int beg = g_off[node], end = g_off[node + 1];
    float a0 = 0.f, a1 = 0.f, a2 = 0.f, a3 = 0.f;
    for (int c = beg; c < end; c += 32) {
        int m = end - c; if (m > 32) m = 32;
        int sidx = (lane < m) ? __ldg(g_src_sorted + c + lane) : 0;
        int i = 0;
        for (; i + 4 <= m; i += 4) {
            int s0 = __shfl_sync(0xFFFFFFFFu, sidx, i);
            int s1 = __shfl_sync(0xFFFFFFFFu, sidx, i + 1);
            int s2 = __shfl_sync(0xFFFFFFFFu, sidx, i + 2);
            int s3 = __shfl_sync(0xFFFFFFFFu, sidx, i + 3);
            uint2 v0 = *(const uint2*)(X + (size_t)s0 * 128 + col);
            uint2 v1 = *(const uint2*)(X + (size_t)s1 * 128 + col);
            uint2 v2 = *(const uint2*)(X + (size_t)s2 * 128 + col);
            uint2 v3 = *(const uint2*)(X + (size_t)s3 * 128 + col);
            float2 f;
            f = __half22float2(*(__half2*)&v0.x); a0 += f.x; a1 += f.y;
            f = __half22float2(*(__half2*)&v0.y); a2 += f.x; a3 += f.y;
            f = __half22float2(*(__half2*)&v1.x); a0 += f.x; a1 += f.y;
            f = __half22float2(*(__half2*)&v1.y); a2 += f.x; a3 += f.y;
            f = __half22float2(*(__half2*)&v2.x); a0 += f.x; a1 += f.y;
            f = __half22float2(*(__half2*)&v2.y); a2 += f.x; a3 += f.y;
            f = __half22float2(*(__half2*)&v3.x); a0 += f.x; a1 += f.y;
            f = __half22float2(*(__half2*)&v3.y); a2 += f.x; a3 += f.y;
        }
        for (; i < m; i++) {
            int s0 = __shfl_sync(0xFFFFFFFFu, sidx, i);
            uint2 v0 = *(const uint2*)(X + (size_t)s0 * 128 + col);
            float2 f;
            f = __half22float2(*(__half2*)&v0.x); a0 += f.x; a1 += f.y;
            f = __half22float2(*(__half2*)&v0.y); a2 += f.x; a3 += f.y;
        }
    }
    float inv = g_inv_deg[node];
    __half2 p0 = __floats2half2_rn(a0 * inv, a1 * inv);
    __half2 p1 = __floats2half2_rn(a2 * inv, a3 * inv);
    uint2 pk;
    pk.x = *(unsigned*)&p0;
    pk.y = *(unsigned*)&p1;
    *(uint2*)(OUT + (size_t)node * 128 + col) = pk;
}

// ---------------- cp.async / ldmatrix / mma helpers ----------------
__device__ __forceinline__ void cp16(void* smem, const void* gmem, bool pred) {
    unsigned saddr = (unsigned)__cvta_generic_to_shared(smem);
    int sz = pred ? 16 : 0;
    asm volatile("cp.async.cg.shared.global [%0], [%1], 16, %2;\n"
                 :: "r"(saddr), "l"(gmem), "r"(sz));
}
__device__ __forceinline__ void cp_commit() {
    asm volatile("cp.async.commit_group;\n");
}
template <int NN>
__device__ __forceinline__ void cp_wait() {
    asm volatile("cp.async.wait_group %0;\n" :: "n"(NN));
}
__device__ __forceinline__ void ldsm_x4(unsigned* r, unsigned saddr) {
    asm volatile("ldmatrix.sync.aligned.m8n8.x4.shared.b16 {%0,%1,%2,%3}, [%4];\n"
                 : "=r"(r[0]), "=r"(r[1]), "=r"(r[2]), "=r"(r[3]) : "r"(saddr));
}
__device__ __forceinline__ void mma_f16(float* c, const unsigned* a, const unsigned* b) {
    asm volatile(
        "mma.sync.aligned.m16n8k16.row.col.f32.f16.f16.f32 "
        "{%0,%1,%2,%3}, {%4,%5,%6,%7}, {%8,%9}, {%0,%1,%2,%3};\n"
        : "+f"(c[0]), "+f"(c[1]), "+f"(c[2]), "+f"(c[3])
        : "r"(a[0]), "r"(a[1]), "r"(a[2]), "r"(a[3]),
          "r"(b[0]), "r"(b[1]));
}

// ---------------- cp.async + ldmatrix double-buffered fp16 GEMM ----------------
// C = [A1|A2] @ Wh^T + bias (optional relu). Wh is [N][K1+K2] fp16 k-contig.
// BM=128, BK=32, 8 warps x 16 rows; warp computes all N cols. RS=40 (conflict-free).
template <int N, typename CT>
__global__ void __launch_bounds__(256)
gemm_cp_kernel(const __half* __restrict__ A1, int K1,
               const __half* __restrict__ A2, int K2,
               const __half* __restrict__ Wh,
               const float* __restrict__ bias, int do_relu,
               CT* __restrict__ C, int Nrows) {
    constexpr int BM = 128, BK = 32, RS = 40;
    constexpr int NT = N / 8;
    constexpr int NP = NT / 2;                  // ldmatrix B pairs
    constexpr int ABUF = BM * RS, WBUF = N * RS;
    __shared__ __align__(16) __half As[2][ABUF];
    __shared__ __align__(16) __half Ws[2][WBUF];

    const int tid  = threadIdx.x;
    const int warp = tid >> 5;
    const int lane = tid & 31;
    const int g  = lane >> 2;
    const int cq = lane & 3;
    const int rowBase = blockIdx.x * BM;
    const int Ktot = K1 + K2;
    const int T = Ktot / BK;

    // ldmatrix per-lane byte offsets (within one buffer)
    const int lr = lane & 7;
    const unsigned aoff =
        (unsigned)(((warp * 16 + ((lane >> 3) & 1) * 8 + lr) * RS + ((lane >> 4) << 3)) * 2);
    const unsigned boff =
        (unsigned)(((((lane >> 4) << 3) + lr) * RS + (((lane >> 3) & 1) << 3)) * 2);
    const unsigned asBase = (unsigned)__cvta_generic_to_shared(&As[0][0]);
    const unsigned wsBase = (unsigned)__cvta_generic_to_shared(&Ws[0][0]);

    float acc[NT][4];
#pragma unroll
    for (int nt = 0; nt < NT; nt++)
#pragma unroll
        for (int i = 0; i < 4; i++) acc[nt][i] = 0.0f;

    auto issue = [&](int tt, int buf) {
        int kbase = tt * BK;
        const __half* A;
        int kloc, Kst;
        if (kbase < K1) { A = A1; kloc = kbase;      Kst = K1; }
        else            { A = A2; kloc = kbase - K1; Kst = K2; }
#pragma unroll
        for (int i = 0; i < 2; i++) {
            int c = tid + 256 * i;
            int row = c >> 2, part = c & 3;
            int grow = rowBase + row;
            const void* src = A + (size_t)grow * Kst + kloc + part * 8;
            cp16(&As[buf][row * RS + part * 8], src, grow < Nrows);
        }
        for (int c = tid; c < N * 4; c += 256) {
            int j = c >> 2, part = c & 3;
            const void* src = Wh + (size_t)j * Ktot + kbase + part * 8;
            cp16(&Ws[buf][j * RS + part * 8], src, true);
        }
    };

    issue(0, 0);
    cp_commit();
    for (int t = 0; t < T; t++) {
        const int buf = t & 1;
        if (t + 1 < T) { issue(t + 1, (t + 1) & 1); cp_commit(); cp_wait<1>(); }
        else           { cp_wait<0>(); }
        __syncthreads();
        const unsigned aB = asBase + (unsigned)(buf * ABUF * 2) + aoff;
        const unsigned wB = wsBase + (unsigned)(buf * WBUF * 2) + boff;
#pragma unroll
        for (int ks = 0; ks < BK; ks += 16) {
            unsigned a[4];
            ldsm_x4(a, aB + ks * 2);
#pragma unroll
            for (int np = 0; np < NP; np++) {
                unsigned b[4];
                ldsm_x4(b, wB + (unsigned)(np * 16 * RS * 2) + ks * 2);
                mma_f16(acc[2 * np],     a, b);
                mma_f16(acc[2 * np + 1], a, b + 2);
            }
        }
        __syncthreads();
    }

    const int row0 = rowBase + warp * 16 + g;
#pragma unroll
    for (int nt = 0; nt < NT; nt++) {
        int col = nt * 8 + 2 * cq;
        float v0 = acc[nt][0], v1 = acc[nt][1], v2 = acc[nt][2], v3 = acc[nt][3];
        if (bias) {
            float bc0 = bias[col], bc1 = bias[col + 1];
            v0 += bc0; v1 += bc1; v2 += bc0; v3 += bc1;
        }
        if (do_relu) {
            v0 = fmaxf(v0, 0.0f); v1 = fmaxf(v1, 0.0f);
            v2 = fmaxf(v2, 0.0f); v3 = fmaxf(v3, 0.0f);
        }
        if (row0 < Nrows) {
            CT* p = C + (size_t)row0 * N + col;
            if (sizeof(CT) == 2) {
                __half2 h = __floats2half2_rn(v0, v1);
                *(unsigned*)p = *(unsigned*)&h;
            } else {
                ((float*)p)[0] = v0; ((float*)p)[1] = v1;
            }
        }
        if (row0 + 8 < Nrows) {
            CT* p = C + (size_t)(row0 + 8) * N + col;
            if (sizeof(CT) == 2) {
                __half2 h = __floats2half2_rn(v2, v3);
                *(unsigned*)p = *(unsigned*)&h;
            } else {
                ((float*)p)[0] = v2; ((float*)p)[1] = v3;
            }
        }
    }
}

// ---------------- fused: mean-agg of t[:, :40] + root + bias + log_softmax ----
__global__ void final_kernel(const float* __restrict__ b3,
                             float* __restrict__ out) {
    int node = (blockIdx.x * blockDim.x + threadIdx.x) >> 5;
    int lane = threadIdx.x & 31;
    if (node >= N_NODES) return;
    int beg = g_off[node], end = g_off[node + 1];
    float a0 = 0.f, a1 = 0.f;
    for (int c = beg; c < end; c += 32) {
        int m = end - c; if (m > 32) m = 32;
        int sidx = (lane < m) ? __ldg(g_src_sorted + c + lane) : 0;
        int i = 0;
        for (; i + 4 <= m; i += 4) {
            int s0 = __shfl_sync(0xFFFFFFFFu, sidx, i);
            int s1 = __shfl_sync(0xFFFFFFFFu, sidx, i + 1);
            int s2 = __shfl_sync(0xFFFFFFFFu, sidx, i + 2);
            int s3 = __shfl_sync(0xFFFFFFFFu, sidx, i + 3);
            const float* r0 = g_t + (size_t)s0 * 80;
            const float* r1 = g_t + (size_t)s1 * 80;
            const float* r2 = g_t + (size_t)s2 * 80;
            const float* r3 = g_t + (size_t)s3 * 80;
            a0 += __ldg(r0 + lane) + __ldg(r1 + lane) + __ldg(r2 + lane) + __ldg(r3 + lane);
            if (lane < 8)
                a1 += __ldg(r0 + 32 + lane) + __ldg(r1 + 32 + lane)
                    + __ldg(r2 + 32 + lane) + __ldg(r3 + 32 + lane);
        }
        for (; i < m; i++) {
            int s0 = __shfl_sync(0xFFFFFFFFu, sidx, i);
            const float* r0 = g_t + (size_t)s0 * 80;
            a0 += __ldg(r0 + lane);
            if (lane < 8) a1 += __ldg(r0 + 32 + lane);
        }
    }
    float inv = g_inv_deg[node];
    const float* tr = g_t + (size_t)node * 80 + 40;
    float v0 = a0 * inv + tr[lane] + b3[lane];
    float v1 = -INFINITY;
    if (lane < 8) v1 = a1 * inv + tr[32 + lane] + b3[32 + lane];
    float m = fmaxf(v0, v1);
#pragma unroll
    for (int s = 16; s; s >>= 1) m = fmaxf(m, __shfl_xor_sync(0xFFFFFFFFu, m, s));
    float e = __expf(v0 - m) + ((lane < 8) ? __expf(v1 - m) : 0.0f);
#pragma unroll
    for (int s = 16; s; s >>= 1) e += __shfl_xor_sync(0xFFFFFFFFu, e, s);
    float lse = m + logf(e);
    float* orow = out + (size_t)node * 40;
    orow[lane] = v0 - lse;
    if (lane < 8) orow[lane + 32] = v1 - lse;
}

// ---------------- launch ----------------
extern "C" void kernel_launch(void* const* d_in, const int* in_sizes, int n_in,
                              void* d_out, int out_size) {
    const float* x    = (const float*)d_in[0];
    const int*   ei   = (const int*)d_in[1];   // [2, E] int32: row0=src, row1=dst
    const float* w1_l = (const float*)d_in[2];
    const float* w1_r = (const float*)d_in[3];
    const float* b1   = (const float*)d_in[4];
    const float* w2_l = (const float*)d_in[5];
    const float* w2_r = (const float*)d_in[6];
    const float* b2   = (const float*)d_in[7];
    const float* w3_l = (const float*)d_in[8];
    const float* w3_r = (const float*)d_in[9];
    const float* b3   = (const float*)d_in[10];
    float* out = (float*)d_out;

    const int* src = ei;
    const int* dst = ei + N_EDGES;

    __half *xh, *agg, *h1, *h2, *wh1, *wh2, *wh3;
    float *t;
    cudaGetSymbolAddress((void**)&xh,  g_xh);
    cudaGetSymbolAddress((void**)&agg, g_agg);
    cudaGetSymbolAddress((void**)&h1,  g_h1);
    cudaGetSymbolAddress((void**)&h2,  g_h2);
    cudaGetSymbolAddress((void**)&t,   g_t);
    cudaGetSymbolAddress((void**)&wh1, g_wh1);
    cudaGetSymbolAddress((void**)&wh2, g_wh2);
    cudaGetSymbolAddress((void**)&wh3, g_wh3);

    const int TB = 256;
    const int convThreads = (N_NODES * 64) / 4;                 // 1.6M
    const int histBlocks  = (convThreads + TB - 1) / TB;
    const int warpBlocks  = (N_NODES * 32 + TB - 1) / TB;       // one warp per node
    const int pairBlocks  = (N_NODES / 2 * 32 + TB - 1) / TB;   // one warp per 2 nodes
    const int gemmBlocks  = (N_NODES + 127) / 128;

    // CSR build + x->fp16 + weight prep (g_count re-zeroed inside scanC)
    hist_conv_kernel<<<histBlocks, TB>>>(dst, x, w1_l, w1_r, w2_l, w2_r, w3_l, w3_r);
    scanA_kernel<<<SCAN_NB, 1024>>>();
    scanC_kernel<<<SCAN_NB, 1024>>>();
    scatter_kernel<<<(N_EDGES + TB - 1) / TB, TB>>>(src, dst);
    sort_kernel<<<warpBlocks, TB>>>();

    // Layer 1: aggregate xh (64), h1 = relu([agg|xh] @ wh1^T + b1)  [fp16 out]
    aggregate64_kernel<<<pairBlocks, TB>>>(xh, agg);
    gemm_cp_kernel<128, __half><<<gemmBlocks, TB>>>(agg, 64, xh, 64, wh1,
                                                    b1, 1, h1, N_NODES);

    // Layer 2: aggregate h1 (128), h2 = relu([agg|h1] @ wh2^T + b2)  [fp16 out]
    aggregate128_kernel<<<warpBlocks, TB>>>(h1, agg);
    gemm_cp_kernel<128, __half><<<gemmBlocks, TB>>>(agg, 128, h1, 128, wh2,
                                                    b2, 1, h2, N_NODES);

    // Layer 3: transform FIRST (linearity), t = h2 @ wh3^T  [fp32 out, 80 wide]
    gemm_cp_kernel<80, float><<<gemmBlocks, TB>>>(h2, 128, (const __half*)0, 0, wh3,
                                                  (const float*)0, 0, t, N_NODES);
    // fused: mean-agg of t[:, :40] + root t[:, 40:] + b3 + log_softmax
    final_kernel<<<warpBlocks, TB>>>(b3, out);
}